// round 14
// baseline (speedup 1.0000x reference)
#include <cuda_runtime.h>
#include <math.h>
#include <stdint.h>

// ---------------- problem constants ----------------
#define N_MAX 10000
#define E_MAX 160000
#define M0 128
#define M1 64
#define DIN 320     // M0 + 3*M1
#define DTP0 192    // M0 + M1
#define DTP1 256    // M0 + 2*M1
#define WNUM 448    // 2*M0 + 3*M1
#define NH 8
#define RAD_IN 32
#define RAD_HID 64

#define INV3 0.5773502691896258f
#define INV2 0.7071067811865476f

#define XSTRIDE 520   // padded per-edge stride for vec tiles (conflict-free dual-half bcast)

typedef unsigned long long ull;

// ---------------- device scratch (static, no allocs) ----------------
__device__ float    g_ms[N_MAX * DIN];
__device__ float    g_md[N_MAX * DIN];
__device__ float    g_w[E_MAX * WNUM];      // radial weights; later reused as value (E,320)
__device__ float    g_ds[E_MAX * DTP0];
__device__ float    g_logits[E_MAX * NH];   // logits, later ex
__device__ float    g_val[E_MAX * DIN];     // val_s(128) + UNgated gated_v(192)
__device__ float    g_gate[E_MAX * M1];
__device__ unsigned g_mx[N_MAX * NH];
__device__ float    g_den[N_MAX * NH];
__device__ float    g_agg[N_MAX * DIN];

// ---------------- helpers ----------------
__device__ __forceinline__ float sigmoidf_(float x) { return 1.f / (1.f + expf(-x)); }
__device__ __forceinline__ float siluf_(float x) { return x * sigmoidf_(x); }
__device__ __forceinline__ float sleakyf_(float x) {
    float sg = sigmoidf_(x);
    return 0.6f * x + 0.4f * x * (2.f * sg - 1.f);
}

// packed f32x2 primitives
__device__ __forceinline__ ull f2pack(float lo, float hi) {
    ull r; asm("mov.b64 %0, {%1, %2};" : "=l"(r) : "f"(lo), "f"(hi)); return r;
}
__device__ __forceinline__ void f2fma(ull& d, ull a, ull b) {
    asm("fma.rn.f32x2 %0, %1, %2, %0;" : "+l"(d) : "l"(a), "l"(b));
}
__device__ __forceinline__ void f2mul(ull& d, ull a, ull b) {
    asm("mul.rn.f32x2 %0, %1, %2;" : "=l"(d) : "l"(a), "l"(b));
}
__device__ __forceinline__ float2 f2unpack(ull v) {
    float2 r; asm("mov.b64 {%0, %1}, %2;" : "=f"(r.x), "=f"(r.y) : "l"(v)); return r;
}

__device__ __forceinline__ void smcpy4(float* dst, const float* __restrict__ src, int n) {
    float4* d = (float4*)dst;
    const float4* s = (const float4*)src;
    int n4 = n >> 2;
    for (int i = threadIdx.x; i < n4; i += blockDim.x) d[i] = s[i];
}

// per-warp row loader
template <int NR, int ROWLEN>
__device__ __forceinline__ void warp_load_rows(float* dst, const float* __restrict__ src,
                                               int r0, int valid, int lane) {
#pragma unroll
    for (int i = 0; i < NR; i++) {
        int r = r0 + i;
        const float* s = src + (size_t)r * ROWLEN;
        bool ok = r < valid;
#pragma unroll
        for (int tt = 0; tt < ROWLEN / 32; tt++) {
            dst[r * ROWLEN + lane + 32 * tt] = ok ? s[lane + 32 * tt] : 0.f;
        }
    }
}

// f32x2 register-tiled GEMM, k-step 2.
template <int KD, int NOSTRIDE, int NP, int RE>
__device__ __forceinline__ void gemm2p(const float* __restrict__ xs,
                                       const float* __restrict__ ws,
                                       ull (&acc)[RE][NP], int lane, int eg, int col0) {
#pragma unroll 2
    for (int k = 0; k < KD; k += 2) {
        ull w0[NP], w1[NP];
#pragma unroll
        for (int p = 0; p < NP; p++) {
            w0[p] = *(const ull*)&ws[k * NOSTRIDE + col0 + 2 * lane + 64 * p];
            w1[p] = *(const ull*)&ws[(k + 1) * NOSTRIDE + col0 + 2 * lane + 64 * p];
        }
#pragma unroll
        for (int i = 0; i < RE; i++) {
            float2 xp = *(const float2*)&xs[(eg * RE + i) * KD + k];
            ull a = f2pack(xp.x, xp.x);
            ull b = f2pack(xp.y, xp.y);
#pragma unroll
            for (int p = 0; p < NP; p++) { f2fma(acc[i][p], a, w0[p]); f2fma(acc[i][p], b, w1[p]); }
        }
    }
}

// Half-warp decomposed vector-GEMM core (gated2/outv2).
// c4 = lane&15 owns cols 4*c4..4*c4+3 (2 ulls via LDS.128 bit-cast, zero weight packs);
// half = lane>>4; warp covers 4 edges: edge = wid*4 + half*2 + i.
// xt rows stride XSTRIDE: [0:128) a, [128:320) q (c*64+j), [320:512) r (c*64+j).
__device__ __forceinline__ void vec_gemm_hw(const float* __restrict__ xt,
                                            const float* __restrict__ ws,
                                            const float* __restrict__ se,
                                            ull (&acc)[2][2][3], int lane, int wid) {
    int c4 = lane & 15;
    int half = lane >> 4;
    int ebase = wid * 4 + half * 2;
    ull accP[2][2] = {};
#pragma unroll 2
    for (int k = 0; k < 128; k += 2) {
        const ull* wp0 = (const ull*)&ws[k * 64 + 4 * c4];
        const ull* wp1 = (const ull*)&ws[(k + 1) * 64 + 4 * c4];
        ull w00 = wp0[0], w01 = wp0[1];
        ull w10 = wp1[0], w11 = wp1[1];
#pragma unroll
        for (int i = 0; i < 2; i++) {
            float2 xp = *(const float2*)&xt[(ebase + i) * XSTRIDE + k];
            ull a = f2pack(xp.x, xp.x);
            ull b = f2pack(xp.y, xp.y);
            f2fma(accP[i][0], a, w00); f2fma(accP[i][1], a, w01);
            f2fma(accP[i][0], b, w10); f2fma(accP[i][1], b, w11);
        }
    }
#pragma unroll
    for (int i = 0; i < 2; i++) {
        const float* see = se + (ebase + i) * 4;
#pragma unroll
        for (int c = 0; c < 3; c++) {
            ull ec = f2pack(see[1 + c], see[1 + c]);
            f2mul(acc[i][0][c], accP[i][0], ec);
            f2mul(acc[i][1][c], accP[i][1], ec);
        }
    }
#pragma unroll 2
    for (int j = 0; j < 64; j += 2) {
        const ull* wp0 = (const ull*)&ws[(128 + j) * 64 + 4 * c4];
        const ull* wp1 = (const ull*)&ws[(129 + j) * 64 + 4 * c4];
        ull w00 = wp0[0], w01 = wp0[1];
        ull w10 = wp1[0], w11 = wp1[1];
#pragma unroll
        for (int i = 0; i < 2; i++) {
            const float* xb = xt + (ebase + i) * XSTRIDE + 128;
#pragma unroll
            for (int c = 0; c < 3; c++) {
                float2 xp = *(const float2*)&xb[c * 64 + j];
                ull a = f2pack(xp.x, xp.x);
                ull b = f2pack(xp.y, xp.y);
                f2fma(acc[i][0][c], a, w00); f2fma(acc[i][1][c], a, w01);
                f2fma(acc[i][0][c], b, w10); f2fma(acc[i][1][c], b, w11);
            }
        }
    }
#pragma unroll 2
    for (int j = 0; j < 64; j += 2) {
        const ull* wp0 = (const ull*)&ws[(192 + j) * 64 + 4 * c4];
        const ull* wp1 = (const ull*)&ws[(193 + j) * 64 + 4 * c4];
        ull w00 = wp0[0], w01 = wp0[1];
        ull w10 = wp1[0], w11 = wp1[1];
#pragma unroll
        for (int i = 0; i < 2; i++) {
            const float* xb = xt + (ebase + i) * XSTRIDE + 320;
#pragma unroll
            for (int c = 0; c < 3; c++) {
                float2 xp = *(const float2*)&xb[c * 64 + j];
                ull a = f2pack(xp.x, xp.x);
                ull b = f2pack(xp.y, xp.y);
                f2fma(acc[i][0][c], a, w00); f2fma(acc[i][1][c], a, w01);
                f2fma(acc[i][0][c], b, w10); f2fma(acc[i][1][c], b, w11);
            }
        }
    }
}

// ---------------- kernels ----------------

__global__ void k_init(int N) {
    int i = blockIdx.x * blockDim.x + threadIdx.x;
    if (i < N * DIN) g_agg[i] = 0.f;
    if (i < N * NH) { g_den[i] = 0.f; g_mx[i] = 0x007FFFFFu; }
}

// node-level linear maps
__global__ void k_node(const float* __restrict__ x,
                       const float* __restrict__ Wss, const float* __restrict__ Wsv,
                       const float* __restrict__ bs,
                       const float* __restrict__ Wds, const float* __restrict__ Wdv,
                       int N) {
    __shared__ float xs[8][DIN];
    int nb = blockIdx.x * 8;
    int tid = threadIdx.x;
    for (int i = tid; i < 8 * DIN; i += 256) {
        int n = i / DIN, j = i % DIN;
        xs[n][j] = (nb + n < N) ? x[(nb + n) * DIN + j] : 0.f;
    }
    __syncthreads();
    int nmax = min(8, N - nb);
    if (nmax <= 0) return;
    for (int o = tid; o < 640; o += 256) {
        float acc[8];
#pragma unroll
        for (int n = 0; n < 8; n++) acc[n] = 0.f;
        if (o < 128) {
            for (int i = 0; i < 128; i++) {
                float w = __ldg(&Wss[i * 128 + o]);
#pragma unroll
                for (int n = 0; n < 8; n++) acc[n] += xs[n][i] * w;
            }
            float b = __ldg(&bs[o]);
            for (int n = 0; n < nmax; n++) g_ms[(nb + n) * DIN + o] = acc[n] + b;
        } else if (o < 320) {
            int k = (o - 128) / 3, c = (o - 128) % 3;
            for (int m = 0; m < 64; m++) {
                float w = __ldg(&Wsv[m * 64 + k]);
#pragma unroll
                for (int n = 0; n < 8; n++) acc[n] += xs[n][128 + m * 3 + c] * w;
            }
            for (int n = 0; n < nmax; n++) g_ms[(nb + n) * DIN + o] = acc[n];
        } else if (o < 448) {
            int k = o - 320;
            for (int i = 0; i < 128; i++) {
                float w = __ldg(&Wds[i * 128 + k]);
#pragma unroll
                for (int n = 0; n < 8; n++) acc[n] += xs[n][i] * w;
            }
            for (int n = 0; n < nmax; n++) g_md[(nb + n) * DIN + k] = acc[n];
        } else {
            int k = (o - 448) / 3, c = (o - 448) % 3;
            for (int m = 0; m < 64; m++) {
                float w = __ldg(&Wdv[m * 64 + k]);
#pragma unroll
                for (int n = 0; n < 8; n++) acc[n] += xs[n][128 + m * 3 + c] * w;
            }
            for (int n = 0; n < nmax; n++) g_md[(nb + n) * DIN + 128 + k * 3 + c] = acc[n];
        }
    }
}

// radial MLP. Tile 128 edges, 16 warps, RE=8, barrier-free per-warp pipeline.
#define RAD_SMEM ((2048 + 28672 + 64 + 448 + 4096 + 8192) * 4)
__global__ void __launch_bounds__(512, 1)
k_rad(const float* __restrict__ es_g, const float* __restrict__ W1,
      const float* __restrict__ b1, const float* __restrict__ W2,
      const float* __restrict__ off, int E) {
    extern __shared__ float sm[];
    float* ws1 = sm;
    float* ws2 = ws1 + 2048;
    float* sb1 = ws2 + 28672;
    float* soff = sb1 + 64;
    float* es = soff + 448;
    float* hid = es + 4096;
    int tid = threadIdx.x;
    smcpy4(ws1, W1, 2048);
    smcpy4(ws2, W2, 28672);
    smcpy4(sb1, b1, 64);
    smcpy4(soff, off, 448);
    __syncthreads();
    int lane = tid & 31, eg = tid >> 5;
    int nt = (E + 127) / 128;
    for (int t = blockIdx.x; t < nt; t += gridDim.x) {
        int base = t * 128;
        int valid = min(128, E - base);
        warp_load_rows<8, RAD_IN>(es, es_g + (size_t)base * RAD_IN, eg * 8, valid, lane);
        __syncwarp();
        {
            ull acc[8][1] = {};
            gemm2p<32, 64, 1, 8>(es, ws1, acc, lane, eg, 0);
#pragma unroll
            for (int i = 0; i < 8; i++) {
                int col = 2 * lane;
                float2 v = f2unpack(acc[i][0]);
                float2 o2;
                o2.x = siluf_(v.x + sb1[col]);
                o2.y = siluf_(v.y + sb1[col + 1]);
                *(float2*)&hid[(eg * 8 + i) * 64 + col] = o2;
            }
        }
        __syncwarp();
        {
            ull acc[8][4] = {};
            gemm2p<64, 448, 4, 8>(hid, ws2, acc, lane, eg, 0);
#pragma unroll
            for (int i = 0; i < 8; i++) {
                int e = eg * 8 + i;
                if (e < valid) {
#pragma unroll
                    for (int p = 0; p < 4; p++) {
                        int col = 2 * lane + 64 * p;
                        float2 v = f2unpack(acc[i][p]);
                        float2 o2; o2.x = v.x + soff[col]; o2.y = v.y + soff[col + 1];
                        *(float2*)&g_w[(size_t)(base + e) * WNUM + col] = o2;
                    }
                }
            }
        }
        {
            ull acc[8][3] = {};
            gemm2p<64, 448, 3, 8>(hid, ws2, acc, lane, eg, 256);
#pragma unroll
            for (int i = 0; i < 8; i++) {
                int e = eg * 8 + i;
                if (e < valid) {
#pragma unroll
                    for (int p = 0; p < 3; p++) {
                        int col = 256 + 2 * lane + 64 * p;
                        float2 v = f2unpack(acc[i][p]);
                        float2 o2; o2.x = v.x + soff[col]; o2.y = v.y + soff[col + 1];
                        *(float2*)&g_w[(size_t)(base + e) * WNUM + col] = o2;
                    }
                }
            }
        }
        __syncwarp();
    }
}

// gated2: register-batched prep (load->compute->store) + half-warp vec-GEMM.
// Tile 64, 16 warps, barrier-free.
#define GATED2_SMEM ((16384 + 64 * XSTRIDE + 256) * 4)
__global__ void __launch_bounds__(512, 1)
k_gated2(const int* __restrict__ esrc, const int* __restrict__ edst,
         const float* __restrict__ eattr, const float* __restrict__ W, int E) {
    extern __shared__ float sm[];
    float* ws = sm;                  // 16384 (256x64)
    float* xt = ws + 16384;          // 64*XSTRIDE
    float* se = xt + 64 * XSTRIDE;   // 64*4
    int tid = threadIdx.x;
    smcpy4(ws, W, 16384);
    __syncthreads();
    int lane = tid & 31, wid = tid >> 5;
    int nt = (E + 63) / 64;
    for (int t = blockIdx.x; t < nt; t += gridDim.x) {
        int base = t * 64;
        int valid = min(64, E - base);
#pragma unroll
        for (int ii = 0; ii < 4; ii++) {
            int le = wid * 4 + ii;
            if (le >= valid) continue;
            int e = base + le;
            int src = __ldg(&esrc[e]), dst = __ldg(&edst[e]);
            const float* ms = g_ms + (size_t)src * DIN;
            const float* md = g_md + (size_t)dst * DIN;
            const float* w = g_w + (size_t)e * WNUM;
            float e0 = __ldg(&eattr[e * 4 + 0]);
            float ex = __ldg(&eattr[e * 4 + 1]);
            float ey = __ldg(&eattr[e * 4 + 2]);
            float ez = __ldg(&eattr[e * 4 + 3]);
            // ---- load phase (registers only) ----
            float msv[4], mdv[4], w1v[4], w2v[4];
#pragma unroll
            for (int tt = 0; tt < 4; tt++) {
                int m = lane + 32 * tt;
                msv[tt] = ms[m]; mdv[tt] = md[m];
                w1v[tt] = w[m];  w2v[tt] = w[128 + m];
            }
            float mvx[2], mvy[2], mvz[2], ddx[2], ddy[2], ddz[2];
            float w3v[2], w4v[2], w5v[2];
#pragma unroll
            for (int tt = 0; tt < 2; tt++) {
                int j = lane + 32 * tt;
                mvx[tt] = ms[128 + j * 3 + 0];
                mvy[tt] = ms[128 + j * 3 + 1];
                mvz[tt] = ms[128 + j * 3 + 2];
                ddx[tt] = md[128 + j * 3 + 0];
                ddy[tt] = md[128 + j * 3 + 1];
                ddz[tt] = md[128 + j * 3 + 2];
                w3v[tt] = w[256 + j]; w4v[tt] = w[320 + j]; w5v[tt] = w[384 + j];
            }
            // ---- compute phase ----
            float dss[4], av[4];
#pragma unroll
            for (int tt = 0; tt < 4; tt++) {
                float s = msv[tt] + mdv[tt];
                dss[tt] = w1v[tt] * s * e0;
                av[tt] = w2v[tt] * s;
            }
            float dsv[2], qx[2], qy[2], qz[2], rx[2], ry[2], rz[2];
#pragma unroll
            for (int tt = 0; tt < 2; tt++) {
                float vx = mvx[tt] + ddx[tt];
                float vy = mvy[tt] + ddy[tt];
                float vz = mvz[tt] + ddz[tt];
                dsv[tt] = w4v[tt] * (vx * ex + vy * ey + vz * ez) * INV3;
                float w3 = w3v[tt] * e0;
                qx[tt] = w3 * vx; qy[tt] = w3 * vy; qz[tt] = w3 * vz;
                float w5 = w5v[tt] * INV2;
                rx[tt] = w5 * (vy * ez - vz * ey);
                ry[tt] = w5 * (vz * ex - vx * ez);
                rz[tt] = w5 * (vx * ey - vy * ex);
            }
            // ---- store phase ----
            if (lane < 4) se[le * 4 + lane] = __ldg(&eattr[e * 4 + lane]);
            float* xr = xt + le * XSTRIDE;
#pragma unroll
            for (int tt = 0; tt < 4; tt++) xr[lane + 32 * tt] = av[tt];
#pragma unroll
            for (int tt = 0; tt < 2; tt++) {
                int j = lane + 32 * tt;
                xr[128 + 0 * 64 + j] = qx[tt];
                xr[128 + 1 * 64 + j] = qy[tt];
                xr[128 + 2 * 64 + j] = qz[tt];
                xr[320 + 0 * 64 + j] = rx[tt];
                xr[320 + 1 * 64 + j] = ry[tt];
                xr[320 + 2 * 64 + j] = rz[tt];
            }
            float* dsr = g_ds + (size_t)e * DTP0;
#pragma unroll
            for (int tt = 0; tt < 4; tt++) dsr[lane + 32 * tt] = dss[tt];
#pragma unroll
            for (int tt = 0; tt < 2; tt++) dsr[128 + lane + 32 * tt] = dsv[tt];
        }
        __syncwarp();
        ull acc[2][2][3];
        vec_gemm_hw(xt, ws, se, acc, lane, wid);
        int c4 = lane & 15;
        int half = lane >> 4;
#pragma unroll
        for (int i = 0; i < 2; i++) {
            int le = wid * 4 + half * 2 + i;
            if (le >= valid) continue;
            size_t ge = (size_t)(base + le);
#pragma unroll
            for (int cu = 0; cu < 2; cu++) {
                int k0 = 4 * c4 + 2 * cu;
#pragma unroll
                for (int c = 0; c < 3; c++) {
                    float2 v = f2unpack(acc[i][cu][c]);
                    g_val[ge * DIN + 128 + k0 * 3 + c] = v.x;
                    g_val[ge * DIN + 128 + (k0 + 1) * 3 + c] = v.y;
                }
            }
        }
        __syncwarp();
    }
}

// logits: tile 128, RE=8, barrier-free; head-dot via warp shuffle reduction.
#define LOG_SMEM ((24576 + 24576 + 128 + 128) * 4)
__global__ void __launch_bounds__(512, 1)
k_logits(const float* __restrict__ Wa, const float* __restrict__ ba,
         const float* __restrict__ ad, int E) {
    extern __shared__ float sm[];
    float* ws = sm;
    float* xs = ws + 24576;
    float* sba = xs + 24576;
    float* sad = sba + 128;
    int tid = threadIdx.x;
    smcpy4(ws, Wa, 24576);
    smcpy4(sba, ba, 128);
    smcpy4(sad, ad, 128);
    __syncthreads();
    int lane = tid & 31, eg = tid >> 5;
    int nt = (E + 127) / 128;
    for (int t = blockIdx.x; t < nt; t += gridDim.x) {
        int base = t * 128;
        int valid = min(128, E - base);
        warp_load_rows<8, DTP0>(xs, g_ds + (size_t)base * DTP0, eg * 8, valid, lane);
        __syncwarp();
        ull acc[8][2] = {};
        gemm2p<192, 128, 2, 8>(xs, ws, acc, lane, eg, 0);
#pragma unroll
        for (int i = 0; i < 8; i++) {
            int e = eg * 8 + i;
            float hsum[2];
#pragma unroll
            for (int p = 0; p < 2; p++) {
                int col = 2 * lane + 64 * p;
                float2 v = f2unpack(acc[i][p]);
                float y0 = sleakyf_(v.x + sba[col]);
                float y1 = sleakyf_(v.y + sba[col + 1]);
                float s = y0 * sad[col] + y1 * sad[col + 1];
                s += __shfl_xor_sync(0xffffffffu, s, 1);
                s += __shfl_xor_sync(0xffffffffu, s, 2);
                s += __shfl_xor_sync(0xffffffffu, s, 4);
                hsum[p] = s;
            }
            if (e < valid && (lane & 7) == 0) {
                size_t ge = (size_t)(base + e);
                g_logits[ge * NH + (lane >> 3)] = hsum[0];
                g_logits[ge * NH + 4 + (lane >> 3)] = hsum[1];
            }
        }
        __syncwarp();
    }
}

// scal: tile 96, RE=6, barrier-free.
#define SCAL_SMEM ((36864 + 18432 + 192) * 4)
__global__ void __launch_bounds__(512, 1)
k_scal(const float* __restrict__ W, const float* __restrict__ b, int E) {
    extern __shared__ float sm[];
    float* ws = sm;
    float* xs = ws + 36864;
    float* sb = xs + 18432;
    int tid = threadIdx.x;
    smcpy4(ws, W, 36864);
    smcpy4(sb, b, 192);
    __syncthreads();
    int lane = tid & 31, eg = tid >> 5;
    int nt = (E + 95) / 96;
    for (int t = blockIdx.x; t < nt; t += gridDim.x) {
        int base = t * 96;
        int valid = min(96, E - base);
        warp_load_rows<6, DTP0>(xs, g_ds + (size_t)base * DTP0, eg * 6, valid, lane);
        __syncwarp();
        ull acc[6][3] = {};
        gemm2p<192, 192, 3, 6>(xs, ws, acc, lane, eg, 0);
#pragma unroll
        for (int i = 0; i < 6; i++) {
            int e = eg * 6 + i;
            if (e >= valid) continue;
            size_t ge = (size_t)(base + e);
#pragma unroll
            for (int p = 0; p < 3; p++) {
                int col = 2 * lane + 64 * p;
                float2 v = f2unpack(acc[i][p]);
                float z0 = v.x + sb[col], z1 = v.y + sb[col + 1];
                if (p < 2) {
                    float2 o2; o2.x = siluf_(z0); o2.y = siluf_(z1);
                    *(float2*)&g_val[ge * DIN + col] = o2;
                } else {
                    float2 o2; o2.x = sigmoidf_(z0); o2.y = sigmoidf_(z1);
                    *(float2*)&g_gate[ge * M1 + col - 128] = o2;
                }
            }
        }
        __syncwarp();
    }
}

// outs2: tile 128, RE=8, barrier-free.
#define OUTS2_SMEM ((24576 + 24576 + 128) * 4)
__global__ void __launch_bounds__(512, 1)
k_outs2(const float* __restrict__ eattr, const float* __restrict__ wi,
        const float* __restrict__ W, const float* __restrict__ b, int E) {
    extern __shared__ float sm[];
    float* ws = sm;
    float* vss = ws + 24576;
    float* sb = vss + 24576;
    int tid = threadIdx.x;
    smcpy4(ws, W, 24576);
    smcpy4(sb, b, 128);
    __syncthreads();
    int lane = tid & 31, wid = tid >> 5;
    int nt = (E + 127) / 128;
    float* gv = g_w;
    for (int t = blockIdx.x; t < nt; t += gridDim.x) {
        int base = t * 128;
        int valid = min(128, E - base);
#pragma unroll
        for (int ii = 0; ii < 8; ii++) {
            int le = wid * 8 + ii;
            if (le >= valid) continue;
            int e = base + le;
            const float* val = g_val + (size_t)e * DIN;
            const float* gt = g_gate + (size_t)e * M1;
            float e0 = __ldg(&eattr[e * 4 + 0]);
            float ex = __ldg(&eattr[e * 4 + 1]);
            float ey = __ldg(&eattr[e * 4 + 2]);
            float ez = __ldg(&eattr[e * 4 + 3]);
            float* vr = vss + le * 192;
#pragma unroll
            for (int tt = 0; tt < 4; tt++) {
                int m = lane + 32 * tt;
                vr[m] = __ldg(&wi[m]) * val[m] * e0;
            }
#pragma unroll
            for (int tt = 0; tt < 2; tt++) {
                int j = lane + 32 * tt;
                float gj = gt[j];
                float d = val[128 + j * 3 + 0] * ex + val[128 + j * 3 + 1] * ey
                        + val[128 + j * 3 + 2] * ez;
                vr[128 + j] = __ldg(&wi[320 + j]) * d * gj * INV3;
            }
        }
        __syncwarp();
        ull acc[8][2] = {};
        gemm2p<192, 128, 2, 8>(vss, ws, acc, lane, wid, 0);
#pragma unroll
        for (int i = 0; i < 8; i++) {
            int e = wid * 8 + i;
            if (e >= valid) continue;
            size_t ge = (size_t)(base + e);
#pragma unroll
            for (int p = 0; p < 2; p++) {
                int col = 2 * lane + 64 * p;
                float2 v = f2unpack(acc[i][p]);
                float2 o2; o2.x = v.x + sb[col]; o2.y = v.y + sb[col + 1];
                *(float2*)&gv[ge * 320 + (col >> 4) * 40 + (col & 15)] = o2;
            }
        }
        __syncwarp();
    }
}

// outv2: register-batched prep + half-warp vec-GEMM. Tile 64, 16 warps, barrier-free.
#define OUTV2_SMEM ((16384 + 64 * XSTRIDE + 256) * 4)
__global__ void __launch_bounds__(512, 1)
k_outv2(const float* __restrict__ eattr, const float* __restrict__ wi,
        const float* __restrict__ W, int E) {
    extern __shared__ float sm[];
    float* ws = sm;
    float* xt = ws + 16384;
    float* se = xt + 64 * XSTRIDE;
    int tid = threadIdx.x;
    smcpy4(ws, W, 16384);
    __syncthreads();
    int lane = tid & 31, wid = tid >> 5;
    int nt = (E + 63) / 64;
    float* gv = g_w;
    for (int t = blockIdx.x; t < nt; t += gridDim.x) {
        int base = t * 64;
        int valid = min(64, E - base);
#pragma unroll
        for (int ii = 0; ii < 4; ii++) {
            int le = wid * 4 + ii;
            if (le >= valid) continue;
            int e = base + le;
            const float* val = g_val + (size_t)e * DIN;
            const float* gt = g_gate + (size_t)e * M1;
            float e0 = __ldg(&eattr[e * 4 + 0]);
            float ex = __ldg(&eattr[e * 4 + 1]);
            float ey = __ldg(&eattr[e * 4 + 2]);
            float ez = __ldg(&eattr[e * 4 + 3]);
            // ---- load phase ----
            float sv[4], wiv[4];
#pragma unroll
            for (int tt = 0; tt < 4; tt++) {
                int m = lane + 32 * tt;
                sv[tt] = val[m];
                wiv[tt] = __ldg(&wi[128 + m]);
            }
            float vx[2], vy[2], vz[2], gj[2], w3v[2], w5v[2];
#pragma unroll
            for (int tt = 0; tt < 2; tt++) {
                int j = lane + 32 * tt;
                vx[tt] = val[128 + j * 3 + 0];
                vy[tt] = val[128 + j * 3 + 1];
                vz[tt] = val[128 + j * 3 + 2];
                gj[tt] = gt[j];
                w3v[tt] = __ldg(&wi[256 + j]);
                w5v[tt] = __ldg(&wi[384 + j]);
            }
            // ---- compute phase ----
            float av[4];
#pragma unroll
            for (int tt = 0; tt < 4; tt++) av[tt] = wiv[tt] * sv[tt];
            float qx[2], qy[2], qz[2], rx[2], ry[2], rz[2];
#pragma unroll
            for (int tt = 0; tt < 2; tt++) {
                float gvx = vx[tt] * gj[tt];
                float gvy = vy[tt] * gj[tt];
                float gvz = vz[tt] * gj[tt];
                float w3 = w3v[tt] * e0;
                qx[tt] = w3 * gvx; qy[tt] = w3 * gvy; qz[tt] = w3 * gvz;
                float w5 = w5v[tt] * INV2;
                rx[tt] = w5 * (gvy * ez - gvz * ey);
                ry[tt] = w5 * (gvz * ex - gvx * ez);
                rz[tt] = w5 * (gvx * ey - gvy * ex);
            }
            // ---- store phase ----
            if (lane < 4) se[le * 4 + lane] = __ldg(&eattr[e * 4 + lane]);
            float* xr = xt + le * XSTRIDE;
#pragma unroll
            for (int tt = 0; tt < 4; tt++) xr[lane + 32 * tt] = av[tt];
#pragma unroll
            for (int tt = 0; tt < 2; tt++) {
                int j = lane + 32 * tt;
                xr[128 + 0 * 64 + j] = qx[tt];
                xr[128 + 1 * 64 + j] = qy[tt];
                xr[128 + 2 * 64 + j] = qz[tt];
                xr[320 + 0 * 64 + j] = rx[tt];
                xr[320 + 1 * 64 + j] = ry[tt];
                xr[320 + 2 * 64 + j] = rz[tt];
            }
        }
        __syncwarp();
        ull acc[2][2][3];
        vec_gemm_hw(xt, ws, se, acc, lane, wid);
        int c4 = lane & 15;
        int half = lane >> 4;
#pragma unroll
        for (int i = 0; i < 2; i++) {
            int le = wid * 4 + half * 2 + i;
            if (le >= valid) continue;
            size_t ge = (size_t)(base + le);
#pragma unroll
            for (int cu = 0; cu < 2; cu++) {
                int k0 = 4 * c4 + 2 * cu;
                int h0 = k0 >> 3, kk0 = k0 & 7;
                int h1 = (k0 + 1) >> 3, kk1 = (k0 + 1) & 7;
#pragma unroll
                for (int c = 0; c < 3; c++) {
                    float2 v = f2unpack(acc[i][cu][c]);
                    gv[ge * 320 + h0 * 40 + 16 + kk0 * 3 + c] = v.x;
                    gv[ge * 320 + h1 * 40 + 16 + kk1 * 3 + c] = v.y;
                }
            }
        }
        __syncwarp();
    }
}

// segment max via encoded-unsigned atomicMax
__global__ void k_max(const int* __restrict__ edst, int E) {
    int i = blockIdx.x * blockDim.x + threadIdx.x;
    if (i >= E * NH) return;
    int e = i >> 3, h = i & 7;
    float x = g_logits[i];
    unsigned bits = __float_as_uint(x);
    unsigned u = (bits & 0x80000000u) ? ~bits : (bits | 0x80000000u);
    atomicMax(&g_mx[edst[e] * NH + h], u);
}

// ex = exp(logit - mx[dst]); den += ex
__global__ void k_expsum(const int* __restrict__ edst, int E) {
    int i = blockIdx.x * blockDim.x + threadIdx.x;
    if (i >= E * NH) return;
    int e = i >> 3, h = i & 7;
    int dst = edst[e];
    unsigned u = g_mx[dst * NH + h];
    unsigned bits = (u & 0x80000000u) ? (u & 0x7FFFFFFFu) : ~u;
    float m = __uint_as_float(bits);
    if (!isfinite(m)) m = 0.f;
    float exv = expf(g_logits[i] - m);
    g_logits[i] = exv;
    atomicAdd(&g_den[dst * NH + h], exv);
}

// agg[dst] += value * alpha ; warp per edge
__global__ void k_agg(const int* __restrict__ edst, int E) {
    int e = (blockIdx.x * blockDim.x + threadIdx.x) >> 5;
    int l = threadIdx.x & 31;
    if (e >= E) return;
    int dst = edst[e];
    float a = 0.f;
    if (l < 8) a = g_logits[(size_t)e * NH + l] / (g_den[dst * NH + l] + 1e-16f);
    const float* val = g_w + (size_t)e * 320;
    float* out = g_agg + (size_t)dst * DIN;
#pragma unroll
    for (int t = 0; t < 10; t++) {
        int i = l + 32 * t;
        int h = i / 40;
        float av = __shfl_sync(0xffffffffu, a, h);
        atomicAdd(&out[i], val[i] * av);
    }
}

// final node projection
__global__ void k_proj(const float* __restrict__ Wps, const float* __restrict__ bp,
                       const float* __restrict__ Wpv, float* __restrict__ out, int N) {
    __shared__ float xs[8][DIN];
    int nb = blockIdx.x * 8;
    int tid = threadIdx.x;
    for (int i = tid; i < 8 * DIN; i += 256) {
        int n = i / DIN, j = i % DIN;
        int gidx;
        if (j < 128) {
            int h = j >> 4;
            gidx = h * 40 + (j & 15);
        } else {
            int m = (j - 128) / 3, c = (j - 128) % 3;
            gidx = (m >> 3) * 40 + 16 + (m & 7) * 3 + c;
        }
        xs[n][j] = (nb + n < N) ? g_agg[(size_t)(nb + n) * DIN + gidx] : 0.f;
    }
    __syncthreads();
    int nmax = min(8, N - nb);
    if (nmax <= 0) return;
    for (int o = tid; o < 320; o += 256) {
        float acc[8];
#pragma unroll
        for (int n = 0; n < 8; n++) acc[n] = 0.f;
        if (o < 128) {
            for (int i = 0; i < 128; i++) {
                float w = __ldg(&Wps[i * 128 + o]);
#pragma unroll
                for (int n = 0; n < 8; n++) acc[n] += xs[n][i] * w;
            }
            float b = __ldg(&bp[o]);
            for (int n = 0; n < nmax; n++) out[(size_t)(nb + n) * DIN + o] = acc[n] + b;
        } else {
            int k = (o - 128) / 3, c = (o - 128) % 3;
            for (int m = 0; m < 64; m++) {
                float w = __ldg(&Wpv[m * 64 + k]);
#pragma unroll
                for (int n = 0; n < 8; n++) acc[n] += xs[n][128 + m * 3 + c] * w;
            }
            for (int n = 0; n < nmax; n++) out[(size_t)(nb + n) * DIN + o] = acc[n];
        }
    }
}

// ---------------- launcher ----------------
extern "C" void kernel_launch(void* const* d_in, const int* in_sizes, int n_in,
                              void* d_out, int out_size) {
    const float* node_input   = (const float*)d_in[0];
    const int*   edge_src     = (const int*)d_in[1];
    const int*   edge_dst     = (const int*)d_in[2];
    const float* edge_attr    = (const float*)d_in[3];
    const float* edge_scalars = (const float*)d_in[4];
    const float* Wsrc_s = (const float*)d_in[5];
    const float* Wsrc_v = (const float*)d_in[6];
    const float* bsrc   = (const float*)d_in[7];
    const float* Wdst_s = (const float*)d_in[8];
    const float* Wdst_v = (const float*)d_in[9];
    const float* rad_W1 = (const float*)d_in[10];
    const float* rad_b1 = (const float*)d_in[11];
    const float* rad_W2 = (const float*)d_in[12];
    const float* rad_off = (const float*)d_in[13];
    const float* Wact_s = (const float*)d_in[14];
    const float* bact   = (const float*)d_in[15];
    const float* Wact_v = (const float*)d_in[16];
    const float* Walpha = (const float*)d_in[17];
    const float* balpha = (const float*)d_in[18];
    const float* w_int  = (const float*)d_in[19];
    const float* Wval_s = (const float*)d_in[20];
    const float* bval   = (const float*)d_in[21];
    const float* Wval_v = (const float*)d_in[22];
    const float* alpha_dot = (const float*)d_in[23];
    const float* Wproj_s = (const float*)d_in[24];
    const float* bproj   = (const float*)d_in[25];
    const float* Wproj_v = (const float*)d_in[26];

    int N = in_sizes[0] / DIN;
    int E = in_sizes[1];

    cudaFuncSetAttribute(k_rad,    cudaFuncAttributeMaxDynamicSharedMemorySize, RAD_SMEM);
    cudaFuncSetAttribute(k_gated2, cudaFuncAttributeMaxDynamicSharedMemorySize, GATED2_SMEM);
    cudaFuncSetAttribute(k_logits, cudaFuncAttributeMaxDynamicSharedMemorySize, LOG_SMEM);
    cudaFuncSetAttribute(k_scal,   cudaFuncAttributeMaxDynamicSharedMemorySize, SCAL_SMEM);
    cudaFuncSetAttribute(k_outs2,  cudaFuncAttributeMaxDynamicSharedMemorySize, OUTS2_SMEM);
    cudaFuncSetAttribute(k_outv2,  cudaFuncAttributeMaxDynamicSharedMemorySize, OUTV2_SMEM);

    const int NB = 148;  // persistent grid, 1 CTA/SM

    k_init<<<(N * DIN + 255) / 256, 256>>>(N);
    k_node<<<(N + 7) / 8, 256>>>(node_input, Wsrc_s, Wsrc_v, bsrc, Wdst_s, Wdst_v, N);
    k_rad<<<NB, 512, RAD_SMEM>>>(edge_scalars, rad_W1, rad_b1, rad_W2, rad_off, E);
    k_gated2<<<NB, 512, GATED2_SMEM>>>(edge_src, edge_dst, edge_attr, Wact_v, E);
    k_logits<<<NB, 512, LOG_SMEM>>>(Walpha, balpha, alpha_dot, E);
    k_scal<<<NB, 512, SCAL_SMEM>>>(Wact_s, bact, E);
    k_outs2<<<NB, 512, OUTS2_SMEM>>>(edge_attr, w_int, Wval_s, bval, E);
    k_outv2<<<NB, 512, OUTV2_SMEM>>>(edge_attr, w_int, Wval_v, E);
    k_max<<<(E * NH + 255) / 256, 256>>>(edge_dst, E);
    k_expsum<<<(E * NH + 255) / 256, 256>>>(edge_dst, E);
    k_agg<<<(E + 7) / 8, 256>>>(edge_dst, E);
    k_proj<<<(N + 7) / 8, 256>>>(Wproj_s, bproj, Wproj_v, (float*)d_out, N);
}

// round 15
// speedup vs baseline: 1.0073x; 1.0073x over previous
#include <cuda_runtime.h>
#include <math.h>
#include <stdint.h>

// ---------------- problem constants ----------------
#define N_MAX 10000
#define E_MAX 160000
#define M0 128
#define M1 64
#define DIN 320     // M0 + 3*M1
#define DTP0 192    // M0 + M1
#define DTP1 256    // M0 + 2*M1
#define WNUM 448    // 2*M0 + 3*M1
#define NH 8
#define RAD_IN 32
#define RAD_HID 64

#define INV3 0.5773502691896258f
#define INV2 0.7071067811865476f

typedef unsigned long long ull;

// ---------------- device scratch (static, no allocs) ----------------
__device__ float    g_ms[N_MAX * DIN];
__device__ float    g_md[N_MAX * DIN];
__device__ float    g_w[E_MAX * WNUM];      // radial weights; later reused as value (E,320)
__device__ float    g_ds[E_MAX * DTP0];
__device__ float    g_logits[E_MAX * NH];   // logits, later ex
__device__ float    g_val[E_MAX * DIN];     // val_s(128) + UNgated gated_v(192)
__device__ float    g_gate[E_MAX * M1];
__device__ unsigned g_mx[N_MAX * NH];
__device__ float    g_den[N_MAX * NH];
__device__ float    g_agg[N_MAX * DIN];

// ---------------- helpers ----------------
__device__ __forceinline__ float sigmoidf_(float x) { return 1.f / (1.f + expf(-x)); }
__device__ __forceinline__ float siluf_(float x) { return x * sigmoidf_(x); }
__device__ __forceinline__ float sleakyf_(float x) {
    float sg = sigmoidf_(x);
    return 0.6f * x + 0.4f * x * (2.f * sg - 1.f);
}

// packed f32x2 primitives
__device__ __forceinline__ ull f2pack(float lo, float hi) {
    ull r; asm("mov.b64 %0, {%1, %2};" : "=l"(r) : "f"(lo), "f"(hi)); return r;
}
__device__ __forceinline__ void f2fma(ull& d, ull a, ull b) {
    asm("fma.rn.f32x2 %0, %1, %2, %0;" : "+l"(d) : "l"(a), "l"(b));
}
__device__ __forceinline__ void f2mul(ull& d, ull a, ull b) {
    asm("mul.rn.f32x2 %0, %1, %2;" : "=l"(d) : "l"(a), "l"(b));
}
__device__ __forceinline__ float2 f2unpack(ull v) {
    float2 r; asm("mov.b64 {%0, %1}, %2;" : "=f"(r.x), "=f"(r.y) : "l"(v)); return r;
}

__device__ __forceinline__ void smcpy4(float* dst, const float* __restrict__ src, int n) {
    float4* d = (float4*)dst;
    const float4* s = (const float4*)src;
    int n4 = n >> 2;
    for (int i = threadIdx.x; i < n4; i += blockDim.x) d[i] = s[i];
}

// per-warp row loader
template <int NR, int ROWLEN>
__device__ __forceinline__ void warp_load_rows(float* dst, const float* __restrict__ src,
                                               int r0, int valid, int lane) {
#pragma unroll
    for (int i = 0; i < NR; i++) {
        int r = r0 + i;
        const float* s = src + (size_t)r * ROWLEN;
        bool ok = r < valid;
#pragma unroll
        for (int tt = 0; tt < ROWLEN / 32; tt++) {
            dst[r * ROWLEN + lane + 32 * tt] = ok ? s[lane + 32 * tt] : 0.f;
        }
    }
}

// f32x2 register-tiled GEMM, k-step 2.
template <int KD, int NOSTRIDE, int NP, int RE>
__device__ __forceinline__ void gemm2p(const float* __restrict__ xs,
                                       const float* __restrict__ ws,
                                       ull (&acc)[RE][NP], int lane, int eg, int col0) {
#pragma unroll 2
    for (int k = 0; k < KD; k += 2) {
        ull w0[NP], w1[NP];
#pragma unroll
        for (int p = 0; p < NP; p++) {
            w0[p] = *(const ull*)&ws[k * NOSTRIDE + col0 + 2 * lane + 64 * p];
            w1[p] = *(const ull*)&ws[(k + 1) * NOSTRIDE + col0 + 2 * lane + 64 * p];
        }
#pragma unroll
        for (int i = 0; i < RE; i++) {
            float2 xp = *(const float2*)&xs[(eg * RE + i) * KD + k];
            ull a = f2pack(xp.x, xp.x);
            ull b = f2pack(xp.y, xp.y);
#pragma unroll
            for (int p = 0; p < NP; p++) { f2fma(acc[i][p], a, w0[p]); f2fma(acc[i][p], b, w1[p]); }
        }
    }
}

// Decomposed vector-GEMM core (gated2/outv2), k-step 2. Warp-local rows.
// xt: per-edge 512 floats: [0:128) a, [128:320) q (c*64+j), [320:512) r (c*64+j)
template <int RE>
__device__ __forceinline__ void vec_gemm_core(const float* __restrict__ xt,
                                              const float* __restrict__ ws,
                                              const float* __restrict__ se,
                                              ull (&acc)[RE][3], int lane, int wid) {
    ull accP[RE] = {};
#pragma unroll 2
    for (int k = 0; k < 128; k += 2) {
        ull w0 = *(const ull*)&ws[k * 64 + 2 * lane];
        ull w1 = *(const ull*)&ws[(k + 1) * 64 + 2 * lane];
#pragma unroll
        for (int i = 0; i < RE; i++) {
            float2 xp = *(const float2*)&xt[(wid * RE + i) * 512 + k];
            f2fma(accP[i], f2pack(xp.x, xp.x), w0);
            f2fma(accP[i], f2pack(xp.y, xp.y), w1);
        }
    }
#pragma unroll
    for (int i = 0; i < RE; i++) {
        const float* see = se + (wid * RE + i) * 4;
#pragma unroll
        for (int c = 0; c < 3; c++) {
            float ec = see[1 + c];
            f2mul(acc[i][c], accP[i], f2pack(ec, ec));
        }
    }
#pragma unroll 2
    for (int k = 0; k < 64; k += 2) {
        ull w0 = *(const ull*)&ws[(128 + k) * 64 + 2 * lane];
        ull w1 = *(const ull*)&ws[(129 + k) * 64 + 2 * lane];
#pragma unroll
        for (int i = 0; i < RE; i++) {
            const float* xb = xt + (wid * RE + i) * 512 + 128;
#pragma unroll
            for (int c = 0; c < 3; c++) {
                float2 xp = *(const float2*)&xb[c * 64 + k];
                f2fma(acc[i][c], f2pack(xp.x, xp.x), w0);
                f2fma(acc[i][c], f2pack(xp.y, xp.y), w1);
            }
        }
    }
#pragma unroll 2
    for (int k = 0; k < 64; k += 2) {
        ull w0 = *(const ull*)&ws[(192 + k) * 64 + 2 * lane];
        ull w1 = *(const ull*)&ws[(193 + k) * 64 + 2 * lane];
#pragma unroll
        for (int i = 0; i < RE; i++) {
            const float* xb = xt + (wid * RE + i) * 512 + 320;
#pragma unroll
            for (int c = 0; c < 3; c++) {
                float2 xp = *(const float2*)&xb[c * 64 + k];
                f2fma(acc[i][c], f2pack(xp.x, xp.x), w0);
                f2fma(acc[i][c], f2pack(xp.y, xp.y), w1);
            }
        }
    }
}

// ---------------- kernels ----------------

__global__ void k_init(int N) {
    int i = blockIdx.x * blockDim.x + threadIdx.x;
    if (i < N * DIN) g_agg[i] = 0.f;
    if (i < N * NH) { g_den[i] = 0.f; g_mx[i] = 0x007FFFFFu; }
}

// node-level linear maps
__global__ void k_node(const float* __restrict__ x,
                       const float* __restrict__ Wss, const float* __restrict__ Wsv,
                       const float* __restrict__ bs,
                       const float* __restrict__ Wds, const float* __restrict__ Wdv,
                       int N) {
    __shared__ float xs[8][DIN];
    int nb = blockIdx.x * 8;
    int tid = threadIdx.x;
    for (int i = tid; i < 8 * DIN; i += 256) {
        int n = i / DIN, j = i % DIN;
        xs[n][j] = (nb + n < N) ? x[(nb + n) * DIN + j] : 0.f;
    }
    __syncthreads();
    int nmax = min(8, N - nb);
    if (nmax <= 0) return;
    for (int o = tid; o < 640; o += 256) {
        float acc[8];
#pragma unroll
        for (int n = 0; n < 8; n++) acc[n] = 0.f;
        if (o < 128) {
            for (int i = 0; i < 128; i++) {
                float w = __ldg(&Wss[i * 128 + o]);
#pragma unroll
                for (int n = 0; n < 8; n++) acc[n] += xs[n][i] * w;
            }
            float b = __ldg(&bs[o]);
            for (int n = 0; n < nmax; n++) g_ms[(nb + n) * DIN + o] = acc[n] + b;
        } else if (o < 320) {
            int k = (o - 128) / 3, c = (o - 128) % 3;
            for (int m = 0; m < 64; m++) {
                float w = __ldg(&Wsv[m * 64 + k]);
#pragma unroll
                for (int n = 0; n < 8; n++) acc[n] += xs[n][128 + m * 3 + c] * w;
            }
            for (int n = 0; n < nmax; n++) g_ms[(nb + n) * DIN + o] = acc[n];
        } else if (o < 448) {
            int k = o - 320;
            for (int i = 0; i < 128; i++) {
                float w = __ldg(&Wds[i * 128 + k]);
#pragma unroll
                for (int n = 0; n < 8; n++) acc[n] += xs[n][i] * w;
            }
            for (int n = 0; n < nmax; n++) g_md[(nb + n) * DIN + k] = acc[n];
        } else {
            int k = (o - 448) / 3, c = (o - 448) % 3;
            for (int m = 0; m < 64; m++) {
                float w = __ldg(&Wdv[m * 64 + k]);
#pragma unroll
                for (int n = 0; n < 8; n++) acc[n] += xs[n][128 + m * 3 + c] * w;
            }
            for (int n = 0; n < nmax; n++) g_md[(nb + n) * DIN + 128 + k * 3 + c] = acc[n];
        }
    }
}

// radial MLP. Tile 128 edges, 16 warps, RE=8, barrier-free per-warp pipeline.
#define RAD_SMEM ((2048 + 28672 + 64 + 448 + 4096 + 8192) * 4)
__global__ void __launch_bounds__(512, 1)
k_rad(const float* __restrict__ es_g, const float* __restrict__ W1,
      const float* __restrict__ b1, const float* __restrict__ W2,
      const float* __restrict__ off, int E) {
    extern __shared__ float sm[];
    float* ws1 = sm;
    float* ws2 = ws1 + 2048;
    float* sb1 = ws2 + 28672;
    float* soff = sb1 + 64;
    float* es = soff + 448;
    float* hid = es + 4096;
    int tid = threadIdx.x;
    smcpy4(ws1, W1, 2048);
    smcpy4(ws2, W2, 28672);
    smcpy4(sb1, b1, 64);
    smcpy4(soff, off, 448);
    __syncthreads();
    int lane = tid & 31, eg = tid >> 5;
    int nt = (E + 127) / 128;
    for (int t = blockIdx.x; t < nt; t += gridDim.x) {
        int base = t * 128;
        int valid = min(128, E - base);
        warp_load_rows<8, RAD_IN>(es, es_g + (size_t)base * RAD_IN, eg * 8, valid, lane);
        __syncwarp();
        {
            ull acc[8][1] = {};
            gemm2p<32, 64, 1, 8>(es, ws1, acc, lane, eg, 0);
#pragma unroll
            for (int i = 0; i < 8; i++) {
                int col = 2 * lane;
                float2 v = f2unpack(acc[i][0]);
                float2 o2;
                o2.x = siluf_(v.x + sb1[col]);
                o2.y = siluf_(v.y + sb1[col + 1]);
                *(float2*)&hid[(eg * 8 + i) * 64 + col] = o2;
            }
        }
        __syncwarp();
        {
            ull acc[8][4] = {};
            gemm2p<64, 448, 4, 8>(hid, ws2, acc, lane, eg, 0);
#pragma unroll
            for (int i = 0; i < 8; i++) {
                int e = eg * 8 + i;
                if (e < valid) {
#pragma unroll
                    for (int p = 0; p < 4; p++) {
                        int col = 2 * lane + 64 * p;
                        float2 v = f2unpack(acc[i][p]);
                        float2 o2; o2.x = v.x + soff[col]; o2.y = v.y + soff[col + 1];
                        *(float2*)&g_w[(size_t)(base + e) * WNUM + col] = o2;
                    }
                }
            }
        }
        {
            ull acc[8][3] = {};
            gemm2p<64, 448, 3, 8>(hid, ws2, acc, lane, eg, 256);
#pragma unroll
            for (int i = 0; i < 8; i++) {
                int e = eg * 8 + i;
                if (e < valid) {
#pragma unroll
                    for (int p = 0; p < 3; p++) {
                        int col = 256 + 2 * lane + 64 * p;
                        float2 v = f2unpack(acc[i][p]);
                        float2 o2; o2.x = v.x + soff[col]; o2.y = v.y + soff[col + 1];
                        *(float2*)&g_w[(size_t)(base + e) * WNUM + col] = o2;
                    }
                }
            }
        }
        __syncwarp();
    }
}

// gated2: register-batched prep (load->compute->store) + full-warp vec-GEMM.
// Tile 64, 16 warps, barrier-free. (R13 champion configuration.)
#define GATED2_SMEM ((16384 + 64 * 512 + 256) * 4)
__global__ void __launch_bounds__(512, 1)
k_gated2(const int* __restrict__ esrc, const int* __restrict__ edst,
         const float* __restrict__ eattr, const float* __restrict__ W, int E) {
    extern __shared__ float sm[];
    float* ws = sm;            // 16384 (256x64)
    float* xt = ws + 16384;    // 64*512
    float* se = xt + 64 * 512; // 64*4
    int tid = threadIdx.x;
    smcpy4(ws, W, 16384);
    __syncthreads();
    int lane = tid & 31, wid = tid >> 5;
    int nt = (E + 63) / 64;
    for (int t = blockIdx.x; t < nt; t += gridDim.x) {
        int base = t * 64;
        int valid = min(64, E - base);
#pragma unroll
        for (int ii = 0; ii < 4; ii++) {
            int le = wid * 4 + ii;
            if (le >= valid) continue;
            int e = base + le;
            int src = __ldg(&esrc[e]), dst = __ldg(&edst[e]);
            const float* ms = g_ms + (size_t)src * DIN;
            const float* md = g_md + (size_t)dst * DIN;
            const float* w = g_w + (size_t)e * WNUM;
            float e0 = __ldg(&eattr[e * 4 + 0]);
            float ex = __ldg(&eattr[e * 4 + 1]);
            float ey = __ldg(&eattr[e * 4 + 2]);
            float ez = __ldg(&eattr[e * 4 + 3]);
            // ---- load phase (registers only) ----
            float msv[4], mdv[4], w1v[4], w2v[4];
#pragma unroll
            for (int tt = 0; tt < 4; tt++) {
                int m = lane + 32 * tt;
                msv[tt] = ms[m]; mdv[tt] = md[m];
                w1v[tt] = w[m];  w2v[tt] = w[128 + m];
            }
            float mvx[2], mvy[2], mvz[2], ddx[2], ddy[2], ddz[2];
            float w3v[2], w4v[2], w5v[2];
#pragma unroll
            for (int tt = 0; tt < 2; tt++) {
                int j = lane + 32 * tt;
                mvx[tt] = ms[128 + j * 3 + 0];
                mvy[tt] = ms[128 + j * 3 + 1];
                mvz[tt] = ms[128 + j * 3 + 2];
                ddx[tt] = md[128 + j * 3 + 0];
                ddy[tt] = md[128 + j * 3 + 1];
                ddz[tt] = md[128 + j * 3 + 2];
                w3v[tt] = w[256 + j]; w4v[tt] = w[320 + j]; w5v[tt] = w[384 + j];
            }
            // ---- compute phase ----
            float dss[4], av[4];
#pragma unroll
            for (int tt = 0; tt < 4; tt++) {
                float s = msv[tt] + mdv[tt];
                dss[tt] = w1v[tt] * s * e0;
                av[tt] = w2v[tt] * s;
            }
            float dsv[2], qx[2], qy[2], qz[2], rx[2], ry[2], rz[2];
#pragma unroll
            for (int tt = 0; tt < 2; tt++) {
                float vx = mvx[tt] + ddx[tt];
                float vy = mvy[tt] + ddy[tt];
                float vz = mvz[tt] + ddz[tt];
                dsv[tt] = w4v[tt] * (vx * ex + vy * ey + vz * ez) * INV3;
                float w3 = w3v[tt] * e0;
                qx[tt] = w3 * vx; qy[tt] = w3 * vy; qz[tt] = w3 * vz;
                float w5 = w5v[tt] * INV2;
                rx[tt] = w5 * (vy * ez - vz * ey);
                ry[tt] = w5 * (vz * ex - vx * ez);
                rz[tt] = w5 * (vx * ey - vy * ex);
            }
            // ---- store phase ----
            if (lane < 4) se[le * 4 + lane] = __ldg(&eattr[e * 4 + lane]);
            float* xr = xt + le * 512;
#pragma unroll
            for (int tt = 0; tt < 4; tt++) xr[lane + 32 * tt] = av[tt];
#pragma unroll
            for (int tt = 0; tt < 2; tt++) {
                int j = lane + 32 * tt;
                xr[128 + 0 * 64 + j] = qx[tt];
                xr[128 + 1 * 64 + j] = qy[tt];
                xr[128 + 2 * 64 + j] = qz[tt];
                xr[320 + 0 * 64 + j] = rx[tt];
                xr[320 + 1 * 64 + j] = ry[tt];
                xr[320 + 2 * 64 + j] = rz[tt];
            }
            float* dsr = g_ds + (size_t)e * DTP0;
#pragma unroll
            for (int tt = 0; tt < 4; tt++) dsr[lane + 32 * tt] = dss[tt];
#pragma unroll
            for (int tt = 0; tt < 2; tt++) dsr[128 + lane + 32 * tt] = dsv[tt];
        }
        __syncwarp();
        ull acc[4][3];
        vec_gemm_core<4>(xt, ws, se, acc, lane, wid);
#pragma unroll
        for (int i = 0; i < 4; i++) {
            int le = wid * 4 + i;
            if (le >= valid) continue;
            size_t ge = (size_t)(base + le);
            int k0 = 2 * lane;
#pragma unroll
            for (int c = 0; c < 3; c++) {
                float2 v = f2unpack(acc[i][c]);
                g_val[ge * DIN + 128 + k0 * 3 + c] = v.x;
                g_val[ge * DIN + 128 + (k0 + 1) * 3 + c] = v.y;
            }
        }
        __syncwarp();
    }
}

// logits: tile 128, RE=8, barrier-free; head-dot via warp shuffle reduction.
#define LOG_SMEM ((24576 + 24576 + 128 + 128) * 4)
__global__ void __launch_bounds__(512, 1)
k_logits(const float* __restrict__ Wa, const float* __restrict__ ba,
         const float* __restrict__ ad, int E) {
    extern __shared__ float sm[];
    float* ws = sm;
    float* xs = ws + 24576;
    float* sba = xs + 24576;
    float* sad = sba + 128;
    int tid = threadIdx.x;
    smcpy4(ws, Wa, 24576);
    smcpy4(sba, ba, 128);
    smcpy4(sad, ad, 128);
    __syncthreads();
    int lane = tid & 31, eg = tid >> 5;
    int nt = (E + 127) / 128;
    for (int t = blockIdx.x; t < nt; t += gridDim.x) {
        int base = t * 128;
        int valid = min(128, E - base);
        warp_load_rows<8, DTP0>(xs, g_ds + (size_t)base * DTP0, eg * 8, valid, lane);
        __syncwarp();
        ull acc[8][2] = {};
        gemm2p<192, 128, 2, 8>(xs, ws, acc, lane, eg, 0);
#pragma unroll
        for (int i = 0; i < 8; i++) {
            int e = eg * 8 + i;
            float hsum[2];
#pragma unroll
            for (int p = 0; p < 2; p++) {
                int col = 2 * lane + 64 * p;
                float2 v = f2unpack(acc[i][p]);
                float y0 = sleakyf_(v.x + sba[col]);
                float y1 = sleakyf_(v.y + sba[col + 1]);
                float s = y0 * sad[col] + y1 * sad[col + 1];
                s += __shfl_xor_sync(0xffffffffu, s, 1);
                s += __shfl_xor_sync(0xffffffffu, s, 2);
                s += __shfl_xor_sync(0xffffffffu, s, 4);
                hsum[p] = s;
            }
            if (e < valid && (lane & 7) == 0) {
                size_t ge = (size_t)(base + e);
                g_logits[ge * NH + (lane >> 3)] = hsum[0];
                g_logits[ge * NH + 4 + (lane >> 3)] = hsum[1];
            }
        }
        __syncwarp();
    }
}

// scal: tile 96, RE=6, barrier-free.
#define SCAL_SMEM ((36864 + 18432 + 192) * 4)
__global__ void __launch_bounds__(512, 1)
k_scal(const float* __restrict__ W, const float* __restrict__ b, int E) {
    extern __shared__ float sm[];
    float* ws = sm;
    float* xs = ws + 36864;
    float* sb = xs + 18432;
    int tid = threadIdx.x;
    smcpy4(ws, W, 36864);
    smcpy4(sb, b, 192);
    __syncthreads();
    int lane = tid & 31, eg = tid >> 5;
    int nt = (E + 95) / 96;
    for (int t = blockIdx.x; t < nt; t += gridDim.x) {
        int base = t * 96;
        int valid = min(96, E - base);
        warp_load_rows<6, DTP0>(xs, g_ds + (size_t)base * DTP0, eg * 6, valid, lane);
        __syncwarp();
        ull acc[6][3] = {};
        gemm2p<192, 192, 3, 6>(xs, ws, acc, lane, eg, 0);
#pragma unroll
        for (int i = 0; i < 6; i++) {
            int e = eg * 6 + i;
            if (e >= valid) continue;
            size_t ge = (size_t)(base + e);
#pragma unroll
            for (int p = 0; p < 3; p++) {
                int col = 2 * lane + 64 * p;
                float2 v = f2unpack(acc[i][p]);
                float z0 = v.x + sb[col], z1 = v.y + sb[col + 1];
                if (p < 2) {
                    float2 o2; o2.x = siluf_(z0); o2.y = siluf_(z1);
                    *(float2*)&g_val[ge * DIN + col] = o2;
                } else {
                    float2 o2; o2.x = sigmoidf_(z0); o2.y = sigmoidf_(z1);
                    *(float2*)&g_gate[ge * M1 + col - 128] = o2;
                }
            }
        }
        __syncwarp();
    }
}

// outs2: tile 128, RE=8, barrier-free.
#define OUTS2_SMEM ((24576 + 24576 + 128) * 4)
__global__ void __launch_bounds__(512, 1)
k_outs2(const float* __restrict__ eattr, const float* __restrict__ wi,
        const float* __restrict__ W, const float* __restrict__ b, int E) {
    extern __shared__ float sm[];
    float* ws = sm;
    float* vss = ws + 24576;
    float* sb = vss + 24576;
    int tid = threadIdx.x;
    smcpy4(ws, W, 24576);
    smcpy4(sb, b, 128);
    __syncthreads();
    int lane = tid & 31, wid = tid >> 5;
    int nt = (E + 127) / 128;
    float* gv = g_w;
    for (int t = blockIdx.x; t < nt; t += gridDim.x) {
        int base = t * 128;
        int valid = min(128, E - base);
#pragma unroll
        for (int ii = 0; ii < 8; ii++) {
            int le = wid * 8 + ii;
            if (le >= valid) continue;
            int e = base + le;
            const float* val = g_val + (size_t)e * DIN;
            const float* gt = g_gate + (size_t)e * M1;
            float e0 = __ldg(&eattr[e * 4 + 0]);
            float ex = __ldg(&eattr[e * 4 + 1]);
            float ey = __ldg(&eattr[e * 4 + 2]);
            float ez = __ldg(&eattr[e * 4 + 3]);
            float* vr = vss + le * 192;
#pragma unroll
            for (int tt = 0; tt < 4; tt++) {
                int m = lane + 32 * tt;
                vr[m] = __ldg(&wi[m]) * val[m] * e0;
            }
#pragma unroll
            for (int tt = 0; tt < 2; tt++) {
                int j = lane + 32 * tt;
                float gj = gt[j];
                float d = val[128 + j * 3 + 0] * ex + val[128 + j * 3 + 1] * ey
                        + val[128 + j * 3 + 2] * ez;
                vr[128 + j] = __ldg(&wi[320 + j]) * d * gj * INV3;
            }
        }
        __syncwarp();
        ull acc[8][2] = {};
        gemm2p<192, 128, 2, 8>(vss, ws, acc, lane, wid, 0);
#pragma unroll
        for (int i = 0; i < 8; i++) {
            int e = wid * 8 + i;
            if (e >= valid) continue;
            size_t ge = (size_t)(base + e);
#pragma unroll
            for (int p = 0; p < 2; p++) {
                int col = 2 * lane + 64 * p;
                float2 v = f2unpack(acc[i][p]);
                float2 o2; o2.x = v.x + sb[col]; o2.y = v.y + sb[col + 1];
                *(float2*)&gv[ge * 320 + (col >> 4) * 40 + (col & 15)] = o2;
            }
        }
        __syncwarp();
    }
}

// outv2: register-batched prep + full-warp vec-GEMM. Tile 64, 16 warps, barrier-free.
#define OUTV2_SMEM ((16384 + 64 * 512 + 256) * 4)
__global__ void __launch_bounds__(512, 1)
k_outv2(const float* __restrict__ eattr, const float* __restrict__ wi,
        const float* __restrict__ W, int E) {
    extern __shared__ float sm[];
    float* ws = sm;
    float* xt = ws + 16384;
    float* se = xt + 64 * 512;
    int tid = threadIdx.x;
    smcpy4(ws, W, 16384);
    __syncthreads();
    int lane = tid & 31, wid = tid >> 5;
    int nt = (E + 63) / 64;
    float* gv = g_w;
    for (int t = blockIdx.x; t < nt; t += gridDim.x) {
        int base = t * 64;
        int valid = min(64, E - base);
#pragma unroll
        for (int ii = 0; ii < 4; ii++) {
            int le = wid * 4 + ii;
            if (le >= valid) continue;
            int e = base + le;
            const float* val = g_val + (size_t)e * DIN;
            const float* gt = g_gate + (size_t)e * M1;
            float e0 = __ldg(&eattr[e * 4 + 0]);
            float ex = __ldg(&eattr[e * 4 + 1]);
            float ey = __ldg(&eattr[e * 4 + 2]);
            float ez = __ldg(&eattr[e * 4 + 3]);
            // ---- load phase (registers only) ----
            float sv[4], wiv[4];
#pragma unroll
            for (int tt = 0; tt < 4; tt++) {
                int m = lane + 32 * tt;
                sv[tt] = val[m];
                wiv[tt] = __ldg(&wi[128 + m]);
            }
            float vx[2], vy[2], vz[2], gj[2], w3v[2], w5v[2];
#pragma unroll
            for (int tt = 0; tt < 2; tt++) {
                int j = lane + 32 * tt;
                vx[tt] = val[128 + j * 3 + 0];
                vy[tt] = val[128 + j * 3 + 1];
                vz[tt] = val[128 + j * 3 + 2];
                gj[tt] = gt[j];
                w3v[tt] = __ldg(&wi[256 + j]);
                w5v[tt] = __ldg(&wi[384 + j]);
            }
            // ---- compute phase ----
            float av[4];
#pragma unroll
            for (int tt = 0; tt < 4; tt++) av[tt] = wiv[tt] * sv[tt];
            float qx[2], qy[2], qz[2], rx[2], ry[2], rz[2];
#pragma unroll
            for (int tt = 0; tt < 2; tt++) {
                float gvx = vx[tt] * gj[tt];
                float gvy = vy[tt] * gj[tt];
                float gvz = vz[tt] * gj[tt];
                float w3 = w3v[tt] * e0;
                qx[tt] = w3 * gvx; qy[tt] = w3 * gvy; qz[tt] = w3 * gvz;
                float w5 = w5v[tt] * INV2;
                rx[tt] = w5 * (gvy * ez - gvz * ey);
                ry[tt] = w5 * (gvz * ex - gvx * ez);
                rz[tt] = w5 * (gvx * ey - gvy * ex);
            }
            // ---- store phase ----
            if (lane < 4) se[le * 4 + lane] = __ldg(&eattr[e * 4 + lane]);
            float* xr = xt + le * 512;
#pragma unroll
            for (int tt = 0; tt < 4; tt++) xr[lane + 32 * tt] = av[tt];
#pragma unroll
            for (int tt = 0; tt < 2; tt++) {
                int j = lane + 32 * tt;
                xr[128 + 0 * 64 + j] = qx[tt];
                xr[128 + 1 * 64 + j] = qy[tt];
                xr[128 + 2 * 64 + j] = qz[tt];
                xr[320 + 0 * 64 + j] = rx[tt];
                xr[320 + 1 * 64 + j] = ry[tt];
                xr[320 + 2 * 64 + j] = rz[tt];
            }
        }
        __syncwarp();
        ull acc[4][3];
        vec_gemm_core<4>(xt, ws, se, acc, lane, wid);
#pragma unroll
        for (int i = 0; i < 4; i++) {
            int le = wid * 4 + i;
            if (le >= valid) continue;
            size_t ge = (size_t)(base + le);
            int k0 = 2 * lane;
            int h0 = k0 >> 3, kk0 = k0 & 7;
            int h1 = (k0 + 1) >> 3, kk1 = (k0 + 1) & 7;
#pragma unroll
            for (int c = 0; c < 3; c++) {
                float2 v = f2unpack(acc[i][c]);
                gv[ge * 320 + h0 * 40 + 16 + kk0 * 3 + c] = v.x;
                gv[ge * 320 + h1 * 40 + 16 + kk1 * 3 + c] = v.y;
            }
        }
        __syncwarp();
    }
}

// segment max via encoded-unsigned atomicMax
__global__ void k_max(const int* __restrict__ edst, int E) {
    int i = blockIdx.x * blockDim.x + threadIdx.x;
    if (i >= E * NH) return;
    int e = i >> 3, h = i & 7;
    float x = g_logits[i];
    unsigned bits = __float_as_uint(x);
    unsigned u = (bits & 0x80000000u) ? ~bits : (bits | 0x80000000u);
    atomicMax(&g_mx[edst[e] * NH + h], u);
}

// ex = exp(logit - mx[dst]); den += ex
__global__ void k_expsum(const int* __restrict__ edst, int E) {
    int i = blockIdx.x * blockDim.x + threadIdx.x;
    if (i >= E * NH) return;
    int e = i >> 3, h = i & 7;
    int dst = edst[e];
    unsigned u = g_mx[dst * NH + h];
    unsigned bits = (u & 0x80000000u) ? (u & 0x7FFFFFFFu) : ~u;
    float m = __uint_as_float(bits);
    if (!isfinite(m)) m = 0.f;
    float exv = expf(g_logits[i] - m);
    g_logits[i] = exv;
    atomicAdd(&g_den[dst * NH + h], exv);
}

// agg[dst] += value * alpha ; warp per edge
__global__ void k_agg(const int* __restrict__ edst, int E) {
    int e = (blockIdx.x * blockDim.x + threadIdx.x) >> 5;
    int l = threadIdx.x & 31;
    if (e >= E) return;
    int dst = edst[e];
    float a = 0.f;
    if (l < 8) a = g_logits[(size_t)e * NH + l] / (g_den[dst * NH + l] + 1e-16f);
    const float* val = g_w + (size_t)e * 320;
    float* out = g_agg + (size_t)dst * DIN;
#pragma unroll
    for (int t = 0; t < 10; t++) {
        int i = l + 32 * t;
        int h = i / 40;
        float av = __shfl_sync(0xffffffffu, a, h);
        atomicAdd(&out[i], val[i] * av);
    }
}

// final node projection
__global__ void k_proj(const float* __restrict__ Wps, const float* __restrict__ bp,
                       const float* __restrict__ Wpv, float* __restrict__ out, int N) {
    __shared__ float xs[8][DIN];
    int nb = blockIdx.x * 8;
    int tid = threadIdx.x;
    for (int i = tid; i < 8 * DIN; i += 256) {
        int n = i / DIN, j = i % DIN;
        int gidx;
        if (j < 128) {
            int h = j >> 4;
            gidx = h * 40 + (j & 15);
        } else {
            int m = (j - 128) / 3, c = (j - 128) % 3;
            gidx = (m >> 3) * 40 + 16 + (m & 7) * 3 + c;
        }
        xs[n][j] = (nb + n < N) ? g_agg[(size_t)(nb + n) * DIN + gidx] : 0.f;
    }
    __syncthreads();
    int nmax = min(8, N - nb);
    if (nmax <= 0) return;
    for (int o = tid; o < 320; o += 256) {
        float acc[8];
#pragma unroll
        for (int n = 0; n < 8; n++) acc[n] = 0.f;
        if (o < 128) {
            for (int i = 0; i < 128; i++) {
                float w = __ldg(&Wps[i * 128 + o]);
#pragma unroll
                for (int n = 0; n < 8; n++) acc[n] += xs[n][i] * w;
            }
            float b = __ldg(&bp[o]);
            for (int n = 0; n < nmax; n++) out[(size_t)(nb + n) * DIN + o] = acc[n] + b;
        } else {
            int k = (o - 128) / 3, c = (o - 128) % 3;
            for (int m = 0; m < 64; m++) {
                float w = __ldg(&Wpv[m * 64 + k]);
#pragma unroll
                for (int n = 0; n < 8; n++) acc[n] += xs[n][128 + m * 3 + c] * w;
            }
            for (int n = 0; n < nmax; n++) out[(size_t)(nb + n) * DIN + o] = acc[n];
        }
    }
}

// ---------------- launcher ----------------
extern "C" void kernel_launch(void* const* d_in, const int* in_sizes, int n_in,
                              void* d_out, int out_size) {
    const float* node_input   = (const float*)d_in[0];
    const int*   edge_src     = (const int*)d_in[1];
    const int*   edge_dst     = (const int*)d_in[2];
    const float* edge_attr    = (const float*)d_in[3];
    const float* edge_scalars = (const float*)d_in[4];
    const float* Wsrc_s = (const float*)d_in[5];
    const float* Wsrc_v = (const float*)d_in[6];
    const float* bsrc   = (const float*)d_in[7];
    const float* Wdst_s = (const float*)d_in[8];
    const float* Wdst_v = (const float*)d_in[9];
    const float* rad_W1 = (const float*)d_in[10];
    const float* rad_b1 = (const float*)d_in[11];
    const float* rad_W2 = (const float*)d_in[12];
    const float* rad_off = (const float*)d_in[13];
    const float* Wact_s = (const float*)d_in[14];
    const float* bact   = (const float*)d_in[15];
    const float* Wact_v = (const float*)d_in[16];
    const float* Walpha = (const float*)d_in[17];
    const float* balpha = (const float*)d_in[18];
    const float* w_int  = (const float*)d_in[19];
    const float* Wval_s = (const float*)d_in[20];
    const float* bval   = (const float*)d_in[21];
    const float* Wval_v = (const float*)d_in[22];
    const float* alpha_dot = (const float*)d_in[23];
    const float* Wproj_s = (const float*)d_in[24];
    const float* bproj   = (const float*)d_in[25];
    const float* Wproj_v = (const float*)d_in[26];

    int N = in_sizes[0] / DIN;
    int E = in_sizes[1];

    cudaFuncSetAttribute(k_rad,    cudaFuncAttributeMaxDynamicSharedMemorySize, RAD_SMEM);
    cudaFuncSetAttribute(k_gated2, cudaFuncAttributeMaxDynamicSharedMemorySize, GATED2_SMEM);
    cudaFuncSetAttribute(k_logits, cudaFuncAttributeMaxDynamicSharedMemorySize, LOG_SMEM);
    cudaFuncSetAttribute(k_scal,   cudaFuncAttributeMaxDynamicSharedMemorySize, SCAL_SMEM);
    cudaFuncSetAttribute(k_outs2,  cudaFuncAttributeMaxDynamicSharedMemorySize, OUTS2_SMEM);
    cudaFuncSetAttribute(k_outv2,  cudaFuncAttributeMaxDynamicSharedMemorySize, OUTV2_SMEM);

    const int NB = 148;  // persistent grid, 1 CTA/SM

    k_init<<<(N * DIN + 255) / 256, 256>>>(N);
    k_node<<<(N + 7) / 8, 256>>>(node_input, Wsrc_s, Wsrc_v, bsrc, Wdst_s, Wdst_v, N);
    k_rad<<<NB, 512, RAD_SMEM>>>(edge_scalars, rad_W1, rad_b1, rad_W2, rad_off, E);
    k_gated2<<<NB, 512, GATED2_SMEM>>>(edge_src, edge_dst, edge_attr, Wact_v, E);
    k_logits<<<NB, 512, LOG_SMEM>>>(Walpha, balpha, alpha_dot, E);
    k_scal<<<NB, 512, SCAL_SMEM>>>(Wact_s, bact, E);
    k_outs2<<<NB, 512, OUTS2_SMEM>>>(edge_attr, w_int, Wval_s, bval, E);
    k_outv2<<<NB, 512, OUTV2_SMEM>>>(edge_attr, w_int, Wval_v, E);
    k_max<<<(E * NH + 255) / 256, 256>>>(edge_dst, E);
    k_expsum<<<(E * NH + 255) / 256, 256>>>(edge_dst, E);
    k_agg<<<(E + 7) / 8, 256>>>(edge_dst, E);
    k_proj<<<(N + 7) / 8, 256>>>(Wproj_s, bproj, Wproj_v, (float*)d_out, N);
}

// round 16
// speedup vs baseline: 1.0121x; 1.0047x over previous
#include <cuda_runtime.h>
#include <math.h>
#include <stdint.h>

// ---------------- problem constants ----------------
#define N_MAX 10000
#define E_MAX 160000
#define M0 128
#define M1 64
#define DIN 320     // M0 + 3*M1
#define DTP0 192    // M0 + M1
#define DTP1 256    // M0 + 2*M1
#define WNUM 448    // 2*M0 + 3*M1
#define NH 8
#define RAD_IN 32
#define RAD_HID 64

#define INV3 0.5773502691896258f
#define INV2 0.7071067811865476f

typedef unsigned long long ull;

// ---------------- device scratch (static, no allocs) ----------------
__device__ float    g_ms[N_MAX * DIN];
__device__ float    g_md[N_MAX * DIN];
__device__ float    g_w[E_MAX * WNUM];      // radial weights; later reused as value (E,320)
__device__ float    g_ds[E_MAX * DTP0];
__device__ float    g_logits[E_MAX * NH];   // stores ex = exp(logit) directly
__device__ float    g_val[E_MAX * DIN];     // val_s(128) + UNgated gated_v(192)
__device__ float    g_gate[E_MAX * M1];
__device__ float    g_den[N_MAX * NH];
__device__ float    g_agg[N_MAX * DIN];

// ---------------- helpers ----------------
__device__ __forceinline__ float sigmoidf_(float x) { return 1.f / (1.f + expf(-x)); }
__device__ __forceinline__ float siluf_(float x) { return x * sigmoidf_(x); }
__device__ __forceinline__ float sleakyf_(float x) {
    float sg = sigmoidf_(x);
    return 0.6f * x + 0.4f * x * (2.f * sg - 1.f);
}

// packed f32x2 primitives
__device__ __forceinline__ ull f2pack(float lo, float hi) {
    ull r; asm("mov.b64 %0, {%1, %2};" : "=l"(r) : "f"(lo), "f"(hi)); return r;
}
__device__ __forceinline__ void f2fma(ull& d, ull a, ull b) {
    asm("fma.rn.f32x2 %0, %1, %2, %0;" : "+l"(d) : "l"(a), "l"(b));
}
__device__ __forceinline__ void f2mul(ull& d, ull a, ull b) {
    asm("mul.rn.f32x2 %0, %1, %2;" : "=l"(d) : "l"(a), "l"(b));
}
__device__ __forceinline__ float2 f2unpack(ull v) {
    float2 r; asm("mov.b64 {%0, %1}, %2;" : "=f"(r.x), "=f"(r.y) : "l"(v)); return r;
}

__device__ __forceinline__ void smcpy4(float* dst, const float* __restrict__ src, int n) {
    float4* d = (float4*)dst;
    const float4* s = (const float4*)src;
    int n4 = n >> 2;
    for (int i = threadIdx.x; i < n4; i += blockDim.x) d[i] = s[i];
}

// per-warp row loader
template <int NR, int ROWLEN>
__device__ __forceinline__ void warp_load_rows(float* dst, const float* __restrict__ src,
                                               int r0, int valid, int lane) {
#pragma unroll
    for (int i = 0; i < NR; i++) {
        int r = r0 + i;
        const float* s = src + (size_t)r * ROWLEN;
        bool ok = r < valid;
#pragma unroll
        for (int tt = 0; tt < ROWLEN / 32; tt++) {
            dst[r * ROWLEN + lane + 32 * tt] = ok ? s[lane + 32 * tt] : 0.f;
        }
    }
}

// f32x2 register-tiled GEMM, k-step 2.
template <int KD, int NOSTRIDE, int NP, int RE>
__device__ __forceinline__ void gemm2p(const float* __restrict__ xs,
                                       const float* __restrict__ ws,
                                       ull (&acc)[RE][NP], int lane, int eg, int col0) {
#pragma unroll 2
    for (int k = 0; k < KD; k += 2) {
        ull w0[NP], w1[NP];
#pragma unroll
        for (int p = 0; p < NP; p++) {
            w0[p] = *(const ull*)&ws[k * NOSTRIDE + col0 + 2 * lane + 64 * p];
            w1[p] = *(const ull*)&ws[(k + 1) * NOSTRIDE + col0 + 2 * lane + 64 * p];
        }
#pragma unroll
        for (int i = 0; i < RE; i++) {
            float2 xp = *(const float2*)&xs[(eg * RE + i) * KD + k];
            ull a = f2pack(xp.x, xp.x);
            ull b = f2pack(xp.y, xp.y);
#pragma unroll
            for (int p = 0; p < NP; p++) { f2fma(acc[i][p], a, w0[p]); f2fma(acc[i][p], b, w1[p]); }
        }
    }
}

// Decomposed vector-GEMM core (gated2/outv2), k-step 2. Warp-local rows.
// xt: per-edge 512 floats: [0:128) a, [128:320) q (c*64+j), [320:512) r (c*64+j)
template <int RE>
__device__ __forceinline__ void vec_gemm_core(const float* __restrict__ xt,
                                              const float* __restrict__ ws,
                                              const float* __restrict__ se,
                                              ull (&acc)[RE][3], int lane, int wid) {
    ull accP[RE] = {};
#pragma unroll 2
    for (int k = 0; k < 128; k += 2) {
        ull w0 = *(const ull*)&ws[k * 64 + 2 * lane];
        ull w1 = *(const ull*)&ws[(k + 1) * 64 + 2 * lane];
#pragma unroll
        for (int i = 0; i < RE; i++) {
            float2 xp = *(const float2*)&xt[(wid * RE + i) * 512 + k];
            f2fma(accP[i], f2pack(xp.x, xp.x), w0);
            f2fma(accP[i], f2pack(xp.y, xp.y), w1);
        }
    }
#pragma unroll
    for (int i = 0; i < RE; i++) {
        const float* see = se + (wid * RE + i) * 4;
#pragma unroll
        for (int c = 0; c < 3; c++) {
            float ec = see[1 + c];
            f2mul(acc[i][c], accP[i], f2pack(ec, ec));
        }
    }
#pragma unroll 2
    for (int k = 0; k < 64; k += 2) {
        ull w0 = *(const ull*)&ws[(128 + k) * 64 + 2 * lane];
        ull w1 = *(const ull*)&ws[(129 + k) * 64 + 2 * lane];
#pragma unroll
        for (int i = 0; i < RE; i++) {
            const float* xb = xt + (wid * RE + i) * 512 + 128;
#pragma unroll
            for (int c = 0; c < 3; c++) {
                float2 xp = *(const float2*)&xb[c * 64 + k];
                f2fma(acc[i][c], f2pack(xp.x, xp.x), w0);
                f2fma(acc[i][c], f2pack(xp.y, xp.y), w1);
            }
        }
    }
#pragma unroll 2
    for (int k = 0; k < 64; k += 2) {
        ull w0 = *(const ull*)&ws[(192 + k) * 64 + 2 * lane];
        ull w1 = *(const ull*)&ws[(193 + k) * 64 + 2 * lane];
#pragma unroll
        for (int i = 0; i < RE; i++) {
            const float* xb = xt + (wid * RE + i) * 512 + 320;
#pragma unroll
            for (int c = 0; c < 3; c++) {
                float2 xp = *(const float2*)&xb[c * 64 + k];
                f2fma(acc[i][c], f2pack(xp.x, xp.x), w0);
                f2fma(acc[i][c], f2pack(xp.y, xp.y), w1);
            }
        }
    }
}

// ---------------- kernels ----------------

__global__ void k_init(int N) {
    int i = blockIdx.x * blockDim.x + threadIdx.x;
    if (i < N * DIN) g_agg[i] = 0.f;
    if (i < N * NH) g_den[i] = 0.f;
}

// node-level linear maps
__global__ void k_node(const float* __restrict__ x,
                       const float* __restrict__ Wss, const float* __restrict__ Wsv,
                       const float* __restrict__ bs,
                       const float* __restrict__ Wds, const float* __restrict__ Wdv,
                       int N) {
    __shared__ float xs[8][DIN];
    int nb = blockIdx.x * 8;
    int tid = threadIdx.x;
    for (int i = tid; i < 8 * DIN; i += 256) {
        int n = i / DIN, j = i % DIN;
        xs[n][j] = (nb + n < N) ? x[(nb + n) * DIN + j] : 0.f;
    }
    __syncthreads();
    int nmax = min(8, N - nb);
    if (nmax <= 0) return;
    for (int o = tid; o < 640; o += 256) {
        float acc[8];
#pragma unroll
        for (int n = 0; n < 8; n++) acc[n] = 0.f;
        if (o < 128) {
            for (int i = 0; i < 128; i++) {
                float w = __ldg(&Wss[i * 128 + o]);
#pragma unroll
                for (int n = 0; n < 8; n++) acc[n] += xs[n][i] * w;
            }
            float b = __ldg(&bs[o]);
            for (int n = 0; n < nmax; n++) g_ms[(nb + n) * DIN + o] = acc[n] + b;
        } else if (o < 320) {
            int k = (o - 128) / 3, c = (o - 128) % 3;
            for (int m = 0; m < 64; m++) {
                float w = __ldg(&Wsv[m * 64 + k]);
#pragma unroll
                for (int n = 0; n < 8; n++) acc[n] += xs[n][128 + m * 3 + c] * w;
            }
            for (int n = 0; n < nmax; n++) g_ms[(nb + n) * DIN + o] = acc[n];
        } else if (o < 448) {
            int k = o - 320;
            for (int i = 0; i < 128; i++) {
                float w = __ldg(&Wds[i * 128 + k]);
#pragma unroll
                for (int n = 0; n < 8; n++) acc[n] += xs[n][i] * w;
            }
            for (int n = 0; n < nmax; n++) g_md[(nb + n) * DIN + k] = acc[n];
        } else {
            int k = (o - 448) / 3, c = (o - 448) % 3;
            for (int m = 0; m < 64; m++) {
                float w = __ldg(&Wdv[m * 64 + k]);
#pragma unroll
                for (int n = 0; n < 8; n++) acc[n] += xs[n][128 + m * 3 + c] * w;
            }
            for (int n = 0; n < nmax; n++) g_md[(nb + n) * DIN + 128 + k * 3 + c] = acc[n];
        }
    }
}

// radial MLP. Tile 128 edges, 16 warps, RE=8, barrier-free per-warp pipeline.
#define RAD_SMEM ((2048 + 28672 + 64 + 448 + 4096 + 8192) * 4)
__global__ void __launch_bounds__(512, 1)
k_rad(const float* __restrict__ es_g, const float* __restrict__ W1,
      const float* __restrict__ b1, const float* __restrict__ W2,
      const float* __restrict__ off, int E) {
    extern __shared__ float sm[];
    float* ws1 = sm;
    float* ws2 = ws1 + 2048;
    float* sb1 = ws2 + 28672;
    float* soff = sb1 + 64;
    float* es = soff + 448;
    float* hid = es + 4096;
    int tid = threadIdx.x;
    smcpy4(ws1, W1, 2048);
    smcpy4(ws2, W2, 28672);
    smcpy4(sb1, b1, 64);
    smcpy4(soff, off, 448);
    __syncthreads();
    int lane = tid & 31, eg = tid >> 5;
    int nt = (E + 127) / 128;
    for (int t = blockIdx.x; t < nt; t += gridDim.x) {
        int base = t * 128;
        int valid = min(128, E - base);
        warp_load_rows<8, RAD_IN>(es, es_g + (size_t)base * RAD_IN, eg * 8, valid, lane);
        __syncwarp();
        {
            ull acc[8][1] = {};
            gemm2p<32, 64, 1, 8>(es, ws1, acc, lane, eg, 0);
#pragma unroll
            for (int i = 0; i < 8; i++) {
                int col = 2 * lane;
                float2 v = f2unpack(acc[i][0]);
                float2 o2;
                o2.x = siluf_(v.x + sb1[col]);
                o2.y = siluf_(v.y + sb1[col + 1]);
                *(float2*)&hid[(eg * 8 + i) * 64 + col] = o2;
            }
        }
        __syncwarp();
        {
            ull acc[8][4] = {};
            gemm2p<64, 448, 4, 8>(hid, ws2, acc, lane, eg, 0);
#pragma unroll
            for (int i = 0; i < 8; i++) {
                int e = eg * 8 + i;
                if (e < valid) {
#pragma unroll
                    for (int p = 0; p < 4; p++) {
                        int col = 2 * lane + 64 * p;
                        float2 v = f2unpack(acc[i][p]);
                        float2 o2; o2.x = v.x + soff[col]; o2.y = v.y + soff[col + 1];
                        *(float2*)&g_w[(size_t)(base + e) * WNUM + col] = o2;
                    }
                }
            }
        }
        {
            ull acc[8][3] = {};
            gemm2p<64, 448, 3, 8>(hid, ws2, acc, lane, eg, 256);
#pragma unroll
            for (int i = 0; i < 8; i++) {
                int e = eg * 8 + i;
                if (e < valid) {
#pragma unroll
                    for (int p = 0; p < 3; p++) {
                        int col = 256 + 2 * lane + 64 * p;
                        float2 v = f2unpack(acc[i][p]);
                        float2 o2; o2.x = v.x + soff[col]; o2.y = v.y + soff[col + 1];
                        *(float2*)&g_w[(size_t)(base + e) * WNUM + col] = o2;
                    }
                }
            }
        }
        __syncwarp();
    }
}

// gated2: register-batched prep (load->compute->store) + full-warp vec-GEMM.
// Tile 64, 16 warps, barrier-free. (R13 champion configuration.)
#define GATED2_SMEM ((16384 + 64 * 512 + 256) * 4)
__global__ void __launch_bounds__(512, 1)
k_gated2(const int* __restrict__ esrc, const int* __restrict__ edst,
         const float* __restrict__ eattr, const float* __restrict__ W, int E) {
    extern __shared__ float sm[];
    float* ws = sm;            // 16384 (256x64)
    float* xt = ws + 16384;    // 64*512
    float* se = xt + 64 * 512; // 64*4
    int tid = threadIdx.x;
    smcpy4(ws, W, 16384);
    __syncthreads();
    int lane = tid & 31, wid = tid >> 5;
    int nt = (E + 63) / 64;
    for (int t = blockIdx.x; t < nt; t += gridDim.x) {
        int base = t * 64;
        int valid = min(64, E - base);
#pragma unroll
        for (int ii = 0; ii < 4; ii++) {
            int le = wid * 4 + ii;
            if (le >= valid) continue;
            int e = base + le;
            int src = __ldg(&esrc[e]), dst = __ldg(&edst[e]);
            const float* ms = g_ms + (size_t)src * DIN;
            const float* md = g_md + (size_t)dst * DIN;
            const float* w = g_w + (size_t)e * WNUM;
            float e0 = __ldg(&eattr[e * 4 + 0]);
            float ex = __ldg(&eattr[e * 4 + 1]);
            float ey = __ldg(&eattr[e * 4 + 2]);
            float ez = __ldg(&eattr[e * 4 + 3]);
            // ---- load phase (registers only) ----
            float msv[4], mdv[4], w1v[4], w2v[4];
#pragma unroll
            for (int tt = 0; tt < 4; tt++) {
                int m = lane + 32 * tt;
                msv[tt] = ms[m]; mdv[tt] = md[m];
                w1v[tt] = w[m];  w2v[tt] = w[128 + m];
            }
            float mvx[2], mvy[2], mvz[2], ddx[2], ddy[2], ddz[2];
            float w3v[2], w4v[2], w5v[2];
#pragma unroll
            for (int tt = 0; tt < 2; tt++) {
                int j = lane + 32 * tt;
                mvx[tt] = ms[128 + j * 3 + 0];
                mvy[tt] = ms[128 + j * 3 + 1];
                mvz[tt] = ms[128 + j * 3 + 2];
                ddx[tt] = md[128 + j * 3 + 0];
                ddy[tt] = md[128 + j * 3 + 1];
                ddz[tt] = md[128 + j * 3 + 2];
                w3v[tt] = w[256 + j]; w4v[tt] = w[320 + j]; w5v[tt] = w[384 + j];
            }
            // ---- compute phase ----
            float dss[4], av[4];
#pragma unroll
            for (int tt = 0; tt < 4; tt++) {
                float s = msv[tt] + mdv[tt];
                dss[tt] = w1v[tt] * s * e0;
                av[tt] = w2v[tt] * s;
            }
            float dsv[2], qx[2], qy[2], qz[2], rx[2], ry[2], rz[2];
#pragma unroll
            for (int tt = 0; tt < 2; tt++) {
                float vx = mvx[tt] + ddx[tt];
                float vy = mvy[tt] + ddy[tt];
                float vz = mvz[tt] + ddz[tt];
                dsv[tt] = w4v[tt] * (vx * ex + vy * ey + vz * ez) * INV3;
                float w3 = w3v[tt] * e0;
                qx[tt] = w3 * vx; qy[tt] = w3 * vy; qz[tt] = w3 * vz;
                float w5 = w5v[tt] * INV2;
                rx[tt] = w5 * (vy * ez - vz * ey);
                ry[tt] = w5 * (vz * ex - vx * ez);
                rz[tt] = w5 * (vx * ey - vy * ex);
            }
            // ---- store phase ----
            if (lane < 4) se[le * 4 + lane] = __ldg(&eattr[e * 4 + lane]);
            float* xr = xt + le * 512;
#pragma unroll
            for (int tt = 0; tt < 4; tt++) xr[lane + 32 * tt] = av[tt];
#pragma unroll
            for (int tt = 0; tt < 2; tt++) {
                int j = lane + 32 * tt;
                xr[128 + 0 * 64 + j] = qx[tt];
                xr[128 + 1 * 64 + j] = qy[tt];
                xr[128 + 2 * 64 + j] = qz[tt];
                xr[320 + 0 * 64 + j] = rx[tt];
                xr[320 + 1 * 64 + j] = ry[tt];
                xr[320 + 2 * 64 + j] = rz[tt];
            }
            float* dsr = g_ds + (size_t)e * DTP0;
#pragma unroll
            for (int tt = 0; tt < 4; tt++) dsr[lane + 32 * tt] = dss[tt];
#pragma unroll
            for (int tt = 0; tt < 2; tt++) dsr[128 + lane + 32 * tt] = dsv[tt];
        }
        __syncwarp();
        ull acc[4][3];
        vec_gemm_core<4>(xt, ws, se, acc, lane, wid);
#pragma unroll
        for (int i = 0; i < 4; i++) {
            int le = wid * 4 + i;
            if (le >= valid) continue;
            size_t ge = (size_t)(base + le);
            int k0 = 2 * lane;
#pragma unroll
            for (int c = 0; c < 3; c++) {
                float2 v = f2unpack(acc[i][c]);
                g_val[ge * DIN + 128 + k0 * 3 + c] = v.x;
                g_val[ge * DIN + 128 + (k0 + 1) * 3 + c] = v.y;
            }
        }
        __syncwarp();
    }
}

// logits: tile 128, RE=8, barrier-free; head-dot via warp shuffle reduction.
// FUSED softmax front-end: stores ex = exp(logit) and accumulates den (no max pass;
// logits are O(10) so raw exp is safe in fp32).
#define LOG_SMEM ((24576 + 24576 + 128 + 128) * 4)
__global__ void __launch_bounds__(512, 1)
k_logits(const int* __restrict__ edst, const float* __restrict__ Wa,
         const float* __restrict__ ba, const float* __restrict__ ad, int E) {
    extern __shared__ float sm[];
    float* ws = sm;
    float* xs = ws + 24576;
    float* sba = xs + 24576;
    float* sad = sba + 128;
    int tid = threadIdx.x;
    smcpy4(ws, Wa, 24576);
    smcpy4(sba, ba, 128);
    smcpy4(sad, ad, 128);
    __syncthreads();
    int lane = tid & 31, eg = tid >> 5;
    int nt = (E + 127) / 128;
    for (int t = blockIdx.x; t < nt; t += gridDim.x) {
        int base = t * 128;
        int valid = min(128, E - base);
        warp_load_rows<8, DTP0>(xs, g_ds + (size_t)base * DTP0, eg * 8, valid, lane);
        __syncwarp();
        ull acc[8][2] = {};
        gemm2p<192, 128, 2, 8>(xs, ws, acc, lane, eg, 0);
#pragma unroll
        for (int i = 0; i < 8; i++) {
            int e = eg * 8 + i;
            float hsum[2];
#pragma unroll
            for (int p = 0; p < 2; p++) {
                int col = 2 * lane + 64 * p;
                float2 v = f2unpack(acc[i][p]);
                float y0 = sleakyf_(v.x + sba[col]);
                float y1 = sleakyf_(v.y + sba[col + 1]);
                float s = y0 * sad[col] + y1 * sad[col + 1];
                s += __shfl_xor_sync(0xffffffffu, s, 1);
                s += __shfl_xor_sync(0xffffffffu, s, 2);
                s += __shfl_xor_sync(0xffffffffu, s, 4);
                hsum[p] = s;
            }
            if (e < valid && (lane & 7) == 0) {
                size_t ge = (size_t)(base + e);
                int dst = __ldg(&edst[base + e]);
                float ex0 = expf(hsum[0]);
                float ex1 = expf(hsum[1]);
                int h = lane >> 3;
                g_logits[ge * NH + h] = ex0;
                g_logits[ge * NH + 4 + h] = ex1;
                atomicAdd(&g_den[dst * NH + h], ex0);
                atomicAdd(&g_den[dst * NH + 4 + h], ex1);
            }
        }
        __syncwarp();
    }
}

// scal: tile 96, RE=6, barrier-free.
#define SCAL_SMEM ((36864 + 18432 + 192) * 4)
__global__ void __launch_bounds__(512, 1)
k_scal(const float* __restrict__ W, const float* __restrict__ b, int E) {
    extern __shared__ float sm[];
    float* ws = sm;
    float* xs = ws + 36864;
    float* sb = xs + 18432;
    int tid = threadIdx.x;
    smcpy4(ws, W, 36864);
    smcpy4(sb, b, 192);
    __syncthreads();
    int lane = tid & 31, eg = tid >> 5;
    int nt = (E + 95) / 96;
    for (int t = blockIdx.x; t < nt; t += gridDim.x) {
        int base = t * 96;
        int valid = min(96, E - base);
        warp_load_rows<6, DTP0>(xs, g_ds + (size_t)base * DTP0, eg * 6, valid, lane);
        __syncwarp();
        ull acc[6][3] = {};
        gemm2p<192, 192, 3, 6>(xs, ws, acc, lane, eg, 0);
#pragma unroll
        for (int i = 0; i < 6; i++) {
            int e = eg * 6 + i;
            if (e >= valid) continue;
            size_t ge = (size_t)(base + e);
#pragma unroll
            for (int p = 0; p < 3; p++) {
                int col = 2 * lane + 64 * p;
                float2 v = f2unpack(acc[i][p]);
                float z0 = v.x + sb[col], z1 = v.y + sb[col + 1];
                if (p < 2) {
                    float2 o2; o2.x = siluf_(z0); o2.y = siluf_(z1);
                    *(float2*)&g_val[ge * DIN + col] = o2;
                } else {
                    float2 o2; o2.x = sigmoidf_(z0); o2.y = sigmoidf_(z1);
                    *(float2*)&g_gate[ge * M1 + col - 128] = o2;
                }
            }
        }
        __syncwarp();
    }
}

// outs2: tile 128, RE=8, barrier-free.
#define OUTS2_SMEM ((24576 + 24576 + 128) * 4)
__global__ void __launch_bounds__(512, 1)
k_outs2(const float* __restrict__ eattr, const float* __restrict__ wi,
        const float* __restrict__ W, const float* __restrict__ b, int E) {
    extern __shared__ float sm[];
    float* ws = sm;
    float* vss = ws + 24576;
    float* sb = vss + 24576;
    int tid = threadIdx.x;
    smcpy4(ws, W, 24576);
    smcpy4(sb, b, 128);
    __syncthreads();
    int lane = tid & 31, wid = tid >> 5;
    int nt = (E + 127) / 128;
    float* gv = g_w;
    for (int t = blockIdx.x; t < nt; t += gridDim.x) {
        int base = t * 128;
        int valid = min(128, E - base);
#pragma unroll
        for (int ii = 0; ii < 8; ii++) {
            int le = wid * 8 + ii;
            if (le >= valid) continue;
            int e = base + le;
            const float* val = g_val + (size_t)e * DIN;
            const float* gt = g_gate + (size_t)e * M1;
            float e0 = __ldg(&eattr[e * 4 + 0]);
            float ex = __ldg(&eattr[e * 4 + 1]);
            float ey = __ldg(&eattr[e * 4 + 2]);
            float ez = __ldg(&eattr[e * 4 + 3]);
            float* vr = vss + le * 192;
#pragma unroll
            for (int tt = 0; tt < 4; tt++) {
                int m = lane + 32 * tt;
                vr[m] = __ldg(&wi[m]) * val[m] * e0;
            }
#pragma unroll
            for (int tt = 0; tt < 2; tt++) {
                int j = lane + 32 * tt;
                float gj = gt[j];
                float d = val[128 + j * 3 + 0] * ex + val[128 + j * 3 + 1] * ey
                        + val[128 + j * 3 + 2] * ez;
                vr[128 + j] = __ldg(&wi[320 + j]) * d * gj * INV3;
            }
        }
        __syncwarp();
        ull acc[8][2] = {};
        gemm2p<192, 128, 2, 8>(vss, ws, acc, lane, wid, 0);
#pragma unroll
        for (int i = 0; i < 8; i++) {
            int e = wid * 8 + i;
            if (e >= valid) continue;
            size_t ge = (size_t)(base + e);
#pragma unroll
            for (int p = 0; p < 2; p++) {
                int col = 2 * lane + 64 * p;
                float2 v = f2unpack(acc[i][p]);
                float2 o2; o2.x = v.x + sb[col]; o2.y = v.y + sb[col + 1];
                *(float2*)&gv[ge * 320 + (col >> 4) * 40 + (col & 15)] = o2;
            }
        }
        __syncwarp();
    }
}

// outv2: tile 64, RE=4, barrier-free (R13 configuration).
#define OUTV2_SMEM ((16384 + 64 * 512 + 256) * 4)
__global__ void __launch_bounds__(512, 1)
k_outv2(const float* __restrict__ eattr, const float* __restrict__ wi,
        const float* __restrict__ W, int E) {
    extern __shared__ float sm[];
    float* ws = sm;
    float* xt = ws + 16384;
    float* se = xt + 64 * 512;
    int tid = threadIdx.x;
    smcpy4(ws, W, 16384);
    __syncthreads();
    int lane = tid & 31, wid = tid >> 5;
    int nt = (E + 63) / 64;
    float* gv = g_w;
    for (int t = blockIdx.x; t < nt; t += gridDim.x) {
        int base = t * 64;
        int valid = min(64, E - base);
#pragma unroll
        for (int ii = 0; ii < 4; ii++) {
            int le = wid * 4 + ii;
            if (le >= valid) continue;
            int e = base + le;
            const float* val = g_val + (size_t)e * DIN;
            const float* gt = g_gate + (size_t)e * M1;
            float e0 = __ldg(&eattr[e * 4 + 0]);
            float ex = __ldg(&eattr[e * 4 + 1]);
            float ey = __ldg(&eattr[e * 4 + 2]);
            float ez = __ldg(&eattr[e * 4 + 3]);
            if (lane < 4) se[le * 4 + lane] = __ldg(&eattr[e * 4 + lane]);
            float* xr = xt + le * 512;
#pragma unroll
            for (int tt = 0; tt < 4; tt++) {
                int m = lane + 32 * tt;
                xr[m] = __ldg(&wi[128 + m]) * val[m];
            }
#pragma unroll
            for (int tt = 0; tt < 2; tt++) {
                int j = lane + 32 * tt;
                float gj = gt[j];
                float vx = val[128 + j * 3 + 0] * gj;
                float vy = val[128 + j * 3 + 1] * gj;
                float vz = val[128 + j * 3 + 2] * gj;
                float w3 = __ldg(&wi[256 + j]) * e0;
                xr[128 + 0 * 64 + j] = w3 * vx;
                xr[128 + 1 * 64 + j] = w3 * vy;
                xr[128 + 2 * 64 + j] = w3 * vz;
                float w5 = __ldg(&wi[384 + j]) * INV2;
                xr[320 + 0 * 64 + j] = w5 * (vy * ez - vz * ey);
                xr[320 + 1 * 64 + j] = w5 * (vz * ex - vx * ez);
                xr[320 + 2 * 64 + j] = w5 * (vx * ey - vy * ex);
            }
        }
        __syncwarp();
        ull acc[4][3];
        vec_gemm_core<4>(xt, ws, se, acc, lane, wid);
#pragma unroll
        for (int i = 0; i < 4; i++) {
            int le = wid * 4 + i;
            if (le >= valid) continue;
            size_t ge = (size_t)(base + le);
            int k0 = 2 * lane;
            int h0 = k0 >> 3, kk0 = k0 & 7;
            int h1 = (k0 + 1) >> 3, kk1 = (k0 + 1) & 7;
#pragma unroll
            for (int c = 0; c < 3; c++) {
                float2 v = f2unpack(acc[i][c]);
                gv[ge * 320 + h0 * 40 + 16 + kk0 * 3 + c] = v.x;
                gv[ge * 320 + h1 * 40 + 16 + kk1 * 3 + c] = v.y;
            }
        }
        __syncwarp();
    }
}

// agg[dst] += value * alpha ; warp per edge (g_logits already holds ex)
__global__ void k_agg(const int* __restrict__ edst, int E) {
    int e = (blockIdx.x * blockDim.x + threadIdx.x) >> 5;
    int l = threadIdx.x & 31;
    if (e >= E) return;
    int dst = edst[e];
    float a = 0.f;
    if (l < 8) a = g_logits[(size_t)e * NH + l] / (g_den[dst * NH + l] + 1e-16f);
    const float* val = g_w + (size_t)e * 320;
    float* out = g_agg + (size_t)dst * DIN;
#pragma unroll
    for (int t = 0; t < 10; t++) {
        int i = l + 32 * t;
        int h = i / 40;
        float av = __shfl_sync(0xffffffffu, a, h);
        atomicAdd(&out[i], val[i] * av);
    }
}

// final node projection
__global__ void k_proj(const float* __restrict__ Wps, const float* __restrict__ bp,
                       const float* __restrict__ Wpv, float* __restrict__ out, int N) {
    __shared__ float xs[8][DIN];
    int nb = blockIdx.x * 8;
    int tid = threadIdx.x;
    for (int i = tid; i < 8 * DIN; i += 256) {
        int n = i / DIN, j = i % DIN;
        int gidx;
        if (j < 128) {
            int h = j >> 4;
            gidx = h * 40 + (j & 15);
        } else {
            int m = (j - 128) / 3, c = (j - 128) % 3;
            gidx = (m >> 3) * 40 + 16 + (m & 7) * 3 + c;
        }
        xs[n][j] = (nb + n < N) ? g_agg[(size_t)(nb + n) * DIN + gidx] : 0.f;
    }
    __syncthreads();
    int nmax = min(8, N - nb);
    if (nmax <= 0) return;
    for (int o = tid; o < 320; o += 256) {
        float acc[8];
#pragma unroll
        for (int n = 0; n < 8; n++) acc[n] = 0.f;
        if (o < 128) {
            for (int i = 0; i < 128; i++) {
                float w = __ldg(&Wps[i * 128 + o]);
#pragma unroll
                for (int n = 0; n < 8; n++) acc[n] += xs[n][i] * w;
            }
            float b = __ldg(&bp[o]);
            for (int n = 0; n < nmax; n++) out[(size_t)(nb + n) * DIN + o] = acc[n] + b;
        } else {
            int k = (o - 128) / 3, c = (o - 128) % 3;
            for (int m = 0; m < 64; m++) {
                float w = __ldg(&Wpv[m * 64 + k]);
#pragma unroll
                for (int n = 0; n < 8; n++) acc[n] += xs[n][128 + m * 3 + c] * w;
            }
            for (int n = 0; n < nmax; n++) out[(size_t)(nb + n) * DIN + o] = acc[n];
        }
    }
}

// ---------------- launcher ----------------
extern "C" void kernel_launch(void* const* d_in, const int* in_sizes, int n_in,
                              void* d_out, int out_size) {
    const float* node_input   = (const float*)d_in[0];
    const int*   edge_src     = (const int*)d_in[1];
    const int*   edge_dst     = (const int*)d_in[2];
    const float* edge_attr    = (const float*)d_in[3];
    const float* edge_scalars = (const float*)d_in[4];
    const float* Wsrc_s = (const float*)d_in[5];
    const float* Wsrc_v = (const float*)d_in[6];
    const float* bsrc   = (const float*)d_in[7];
    const float* Wdst_s = (const float*)d_in[8];
    const float* Wdst_v = (const float*)d_in[9];
    const float* rad_W1 = (const float*)d_in[10];
    const float* rad_b1 = (const float*)d_in[11];
    const float* rad_W2 = (const float*)d_in[12];
    const float* rad_off = (const float*)d_in[13];
    const float* Wact_s = (const float*)d_in[14];
    const float* bact   = (const float*)d_in[15];
    const float* Wact_v = (const float*)d_in[16];
    const float* Walpha = (const float*)d_in[17];
    const float* balpha = (const float*)d_in[18];
    const float* w_int  = (const float*)d_in[19];
    const float* Wval_s = (const float*)d_in[20];
    const float* bval   = (const float*)d_in[21];
    const float* Wval_v = (const float*)d_in[22];
    const float* alpha_dot = (const float*)d_in[23];
    const float* Wproj_s = (const float*)d_in[24];
    const float* bproj   = (const float*)d_in[25];
    const float* Wproj_v = (const float*)d_in[26];

    int N = in_sizes[0] / DIN;
    int E = in_sizes[1];

    cudaFuncSetAttribute(k_rad,    cudaFuncAttributeMaxDynamicSharedMemorySize, RAD_SMEM);
    cudaFuncSetAttribute(k_gated2, cudaFuncAttributeMaxDynamicSharedMemorySize, GATED2_SMEM);
    cudaFuncSetAttribute(k_logits, cudaFuncAttributeMaxDynamicSharedMemorySize, LOG_SMEM);
    cudaFuncSetAttribute(k_scal,   cudaFuncAttributeMaxDynamicSharedMemorySize, SCAL_SMEM);
    cudaFuncSetAttribute(k_outs2,  cudaFuncAttributeMaxDynamicSharedMemorySize, OUTS2_SMEM);
    cudaFuncSetAttribute(k_outv2,  cudaFuncAttributeMaxDynamicSharedMemorySize, OUTV2_SMEM);

    const int NB = 148;  // persistent grid, 1 CTA/SM

    k_init<<<(N * DIN + 255) / 256, 256>>>(N);
    k_node<<<(N + 7) / 8, 256>>>(node_input, Wsrc_s, Wsrc_v, bsrc, Wdst_s, Wdst_v, N);
    k_rad<<<NB, 512, RAD_SMEM>>>(edge_scalars, rad_W1, rad_b1, rad_W2, rad_off, E);
    k_gated2<<<NB, 512, GATED2_SMEM>>>(edge_src, edge_dst, edge_attr, Wact_v, E);
    k_logits<<<NB, 512, LOG_SMEM>>>(edge_dst, Walpha, balpha, alpha_dot, E);
    k_scal<<<NB, 512, SCAL_SMEM>>>(Wact_s, bact, E);
    k_outs2<<<NB, 512, OUTS2_SMEM>>>(edge_attr, w_int, Wval_s, bval, E);
    k_outv2<<<NB, 512, OUTV2_SMEM>>>(edge_attr, w_int, Wval_v, E);
    k_agg<<<(E + 7) / 8, 256>>>(edge_dst, E);
    k_proj<<<(N + 7) / 8, 256>>>(Wproj_s, bproj, Wproj_v, (float*)d_out, N);
}